// round 14
// baseline (speedup 1.0000x reference)
#include <cuda_runtime.h>
#include <cuda_bf16.h>
#include <math.h>

typedef unsigned long long ull;
typedef unsigned int u32;

// ---------------- problem constants ----------------
#define NN        2048
#define P1        14
#define H0DIM     1728
#define HDIM      512
#define H2DIM     1024
#define TDIM      10
#define NSPLIT    16

// conv SMEM layout (floats)
#define S_IMG     0
#define S_W1      1056
#define S_B1      1632
#define S_B2      1668
#define S_POOL1   1716
#define S_W2      8772
#define W2STRIDE  50
#define S_TOTALF  (8772 + 16200)

#define SWZ(off)  ((off) ^ (((off) >> 3) & 0x70))

// ---------------- scratch ----------------
__device__ float g_H2[(size_t)NN * H2DIM];
__device__ float g_An[(size_t)NN * HDIM];
__device__ float g_P[(size_t)NN * H2DIM];
__device__ float g_L[TDIM * NN];
__device__ float g_betas[TDIM * NN];
__device__ float g_embs_part[NSPLIT * TDIM * H2DIM];
__device__ float g_embs[TDIM * H2DIM];
__device__ float g_V[TDIM * 128];

__device__ __align__(256) __nv_bfloat16 g_H0s[(size_t)NN * 3 * H0DIM];
__device__ __align__(256) __nv_bfloat16 g_H1s[(size_t)NN * 3 * HDIM];
__device__ __align__(256) __nv_bfloat16 g_H2s[(size_t)NN * 3 * H2DIM];
__device__ __align__(256) __nv_bfloat16 g_fc1ws[(size_t)HDIM * 3 * H0DIM];
__device__ __align__(256) __nv_bfloat16 g_fc2ws[(size_t)HDIM * 3 * HDIM];
__device__ __align__(256) __nv_bfloat16 g_nbrws[(size_t)HDIM * 3 * HDIM];
__device__ __align__(256) __nv_bfloat16 g_protows[(size_t)H2DIM * 3 * H2DIM];

__global__ void noop_kernel() {}

__device__ __forceinline__ u32 smem_u32(const void* p) {
    u32 a; asm("{ .reg .u64 t; cvta.to.shared.u64 t, %1; cvt.u32.u64 %0, t; }" : "=r"(a) : "l"(p));
    return a;
}
__device__ __forceinline__ void cp16(u32 dst, const void* src) {
    asm volatile("cp.async.ca.shared.global [%0], [%1], 16;" :: "r"(dst), "l"(src));
}
__device__ __forceinline__ void cp_commit() { asm volatile("cp.async.commit_group;" ::: "memory"); }
template <int N>
__device__ __forceinline__ void cp_wait() { asm volatile("cp.async.wait_group %0;" :: "n"(N) : "memory"); }

// ---------------- merged weight split cvt ----------------
#define CVT_N1 884736
#define CVT_N2 262144
#define CVT_N3 262144
#define CVT_N4 1048576
__global__ void cvt_all_kernel(const float* __restrict__ w1m, const float* __restrict__ w2m,
                               const float* __restrict__ w3m, const float* __restrict__ w4m) {
    int idx = blockIdx.x * 256 + threadIdx.x;
    const float* w; __nv_bfloat16* o; int K; int li;
    if (idx < CVT_N1) { w = w1m; o = g_fc1ws; K = H0DIM; li = idx; }
    else if (idx < CVT_N1 + CVT_N2) { w = w2m; o = g_fc2ws; K = HDIM; li = idx - CVT_N1; }
    else if (idx < CVT_N1 + CVT_N2 + CVT_N3) { w = w3m; o = g_nbrws; K = HDIM; li = idx - CVT_N1 - CVT_N2; }
    else if (idx < CVT_N1 + CVT_N2 + CVT_N3 + CVT_N4) { w = w4m; o = g_protows; K = H2DIM; li = idx - CVT_N1 - CVT_N2 - CVT_N3; }
    else return;
    int n = li / K, k = li - n * K;
    float v = w[li];
    __nv_bfloat16 hi = __float2bfloat16(v);
    __nv_bfloat16 lo = __float2bfloat16(v - __bfloat162float(hi));
    size_t base = (size_t)n * 3 * K + k;
    o[base] = hi; o[base + K] = lo; o[base + 2 * K] = hi;
}

// ---------------- fused conv (R7/R10-proven config) ----------------
__device__ __forceinline__ ull pack2(float lo, float hi) {
    ull r; asm("mov.b64 %0, {%1, %2};" : "=l"(r) : "f"(lo), "f"(hi)); return r;
}
__device__ __forceinline__ void unpack2(ull v, float& lo, float& hi) {
    asm("mov.b64 {%0, %1}, %2;" : "=f"(lo), "=f"(hi) : "l"(v));
}
__device__ __forceinline__ void fma2(ull& d, ull a, ull b) {
    asm("fma.rn.f32x2 %0, %1, %2, %0;" : "+l"(d) : "l"(a), "l"(b));
}

__global__ __launch_bounds__(512, 2)
void conv_fused_kernel(const float* __restrict__ x,
                       const float* __restrict__ w1,
                       const float* __restrict__ b1,
                       const float* __restrict__ w2,
                       const float* __restrict__ b2) {
    extern __shared__ float sm[];
    float* s_img   = sm + S_IMG;
    float* s_w1    = sm + S_W1;
    float* s_b1    = sm + S_B1;
    float* s_b2    = sm + S_B2;
    float* s_pool1 = sm + S_POOL1;
    float* s_w2    = sm + S_W2;

    int n = blockIdx.x, tid = threadIdx.x;
    const float* xin = x + (size_t)n * 1024;

    for (int i = tid; i < 1024; i += 512) {
        int r = i >> 5, c = i & 31;
        s_img[r * 33 + c] = xin[i];
    }
    for (int i = tid; i < 576; i += 512) s_w1[i] = w1[i];
    if (tid < 36) s_b1[tid] = b1[tid];
    else if (tid >= 64 && tid < 112) s_b2[tid - 64] = b2[tid - 64];
    for (int i = tid; i < 15552; i += 512) {
        int ch = i / 324, r = i - ch * 324;
        s_w2[r * W2STRIDE + ch] = w2[i];
    }
    __syncthreads();

    if (tid < 504) {
        int ch = tid / 14, py = tid % 14;
        const float4* wp = (const float4*)&s_w1[ch * 16];
        float4 a0 = wp[0], a1 = wp[1], a2 = wp[2], a3 = wp[3];
        float wr[16] = {a0.x,a0.y,a0.z,a0.w, a1.x,a1.y,a1.z,a1.w,
                        a2.x,a2.y,a2.z,a2.w, a3.x,a3.y,a3.z,a3.w};
        float bias1 = s_b1[ch];
        float* prow = s_pool1 + ch * 196 + py * 14;
        const float* ibase = s_img + (2 * py) * 33;
        for (int px = 0; px < 14; px++) {
            float s00 = 0.f, s01 = 0.f, s10 = 0.f, s11 = 0.f;
            const float* ip = ibase + 2 * px;
            #pragma unroll
            for (int yy = 0; yy < 5; yy++) {
                float r0 = ip[yy * 33 + 0], r1 = ip[yy * 33 + 1], r2 = ip[yy * 33 + 2];
                float r3 = ip[yy * 33 + 3], r4 = ip[yy * 33 + 4];
                if (yy <= 3) {
                    const float* w = wr + yy * 4;
                    s00 += r0 * w[0] + r1 * w[1] + r2 * w[2] + r3 * w[3];
                    s01 += r1 * w[0] + r2 * w[1] + r3 * w[2] + r4 * w[3];
                }
                if (yy >= 1) {
                    const float* w = wr + (yy - 1) * 4;
                    s10 += r0 * w[0] + r1 * w[1] + r2 * w[2] + r3 * w[3];
                    s11 += r1 * w[0] + r2 * w[1] + r3 * w[2] + r4 * w[3];
                }
            }
            float m = fmaxf(fmaxf(s00, s01), fmaxf(s10, s11));
            prow[px] = fmaxf(m + bias1, 0.f);
        }
    }
    __syncthreads();

    // conv2: thread = (16-ch group g, position pair q/q+72)
    ull acc0[8], acc1[8];
    int g = tid / 72, q = tid - g * 72;
    if (tid < 216) {
        int cy = q / 12, cx = q - cy * 12;
        #pragma unroll
        for (int j = 0; j < 8; j++) { acc0[j] = 0ull; acc1[j] = 0ull; }
        const float* in0 = s_pool1 + cy * 14 + cx;
        const float* in1 = in0 + 84;
        const float* wgb = s_w2 + g * 16;
        for (int c = 0; c < 36; c++) {
            #pragma unroll
            for (int k = 0; k < 9; k++) {
                int ioff = c * 196 + (k / 3) * 14 + (k % 3);
                float v0 = in0[ioff], v1 = in1[ioff];
                ull vv0 = pack2(v0, v0), vv1 = pack2(v1, v1);
                const ull* qw = (const ull*)(wgb + (c * 9 + k) * W2STRIDE);
                #pragma unroll
                for (int j = 0; j < 8; j++) {
                    ull w = qw[j];
                    fma2(acc0[j], w, vv0);
                    fma2(acc1[j], w, vv1);
                }
            }
        }
    }
    __syncthreads();
    if (tid < 216) {
        float* o0 = s_w2 + q * 49 + g * 16;
        float* o1 = s_w2 + (q + 72) * 49 + g * 16;
        #pragma unroll
        for (int j = 0; j < 8; j++) {
            float lo, hi;
            unpack2(acc0[j], lo, hi); o0[2 * j] = lo; o0[2 * j + 1] = hi;
            unpack2(acc1[j], lo, hi); o1[2 * j] = lo; o1[2 * j + 1] = hi;
        }
    }
    __syncthreads();

    __nv_bfloat16* outb = g_H0s + (size_t)n * 3 * H0DIM;
    for (int o = tid; o < 1728; o += 512) {
        int ch = o / 36, pp = o - ch * 36;
        int py = pp / 6, px = pp - py * 6;
        int i00 = (2 * py) * 12 + 2 * px;
        float m = fmaxf(fmaxf(s_w2[i00 * 49 + ch],        s_w2[(i00 + 1)  * 49 + ch]),
                        fmaxf(s_w2[(i00 + 12) * 49 + ch], s_w2[(i00 + 13) * 49 + ch]));
        float v = fmaxf(m + s_b2[ch], 0.f);
        __nv_bfloat16 hi = __float2bfloat16(v);
        __nv_bfloat16 lo = __float2bfloat16(v - __bfloat162float(hi));
        outb[o] = hi; outb[1728 + o] = hi; outb[3456 + o] = lo;
    }
}

// ---------------- mma.sync bf16 GEMM 128x64, 16 warps, 4-stage cp.async -------
// Warp tile 32(M) x 16(N): wm = wid & 3, wn = wid >> 2. Doubles warps/SM vs the
// 8-warp config (grid 128 on 148 SMs -> warps/SM is the binding constraint).
#define STAGE_BYTES 24576
template <int ACT, bool WF, bool WS>
__global__ __launch_bounds__(512)
void mma_gemm(const __nv_bfloat16* __restrict__ A, const __nv_bfloat16* __restrict__ B,
              const float* __restrict__ bias, float* __restrict__ Cf, __nv_bfloat16* __restrict__ Cs,
              int K, int rsA, int ssA, int rsB, int ssB, int ldc, int ldcs, int slotC) {
    extern __shared__ char smem[];
    u32 sb = smem_u32(smem);
    const int tid = threadIdx.x, wid = tid >> 5, lane = tid & 31;
    const int bm = blockIdx.y * 128, bn = blockIdx.x * 64;
    const int wm = wid & 3, wn = wid >> 2;
    const int lr = tid >> 3, lg = tid & 7;    // 64 rows x 8 groups per pass

    auto cp_tile = [&](int kc, int buf) {   // kc in elements (multiple of 64)
        int slot = kc / K, off = kc - slot * K;
        u32 base = sb + buf * STAGE_BYTES;
        const __nv_bfloat16* Ab = A + (size_t)bm * rsA + (size_t)slot * ssA + off;
        #pragma unroll
        for (int i = 0; i < 2; i++)
            cp16(base + SWZ((lr + i * 64) * 128 + lg * 16), Ab + (size_t)(lr + i * 64) * rsA + lg * 8);
        const __nv_bfloat16* Bb = B + (size_t)bn * rsB + (size_t)slot * ssB + off;
        cp16(base + 16384 + SWZ(lr * 128 + lg * 16), Bb + (size_t)lr * rsB + lg * 8);
    };

    float acc[2][2][4];
    #pragma unroll
    for (int mi = 0; mi < 2; mi++)
        #pragma unroll
        for (int ni = 0; ni < 2; ni++)
            #pragma unroll
            for (int j = 0; j < 4; j++) acc[mi][ni][j] = 0.f;

    const int nch = (3 * K) / 64;
    cp_tile(0, 0); cp_commit();
    cp_tile(64, 1); cp_commit();
    cp_tile(128, 2); cp_commit();

    for (int c = 0; c < nch; c++) {
        if (c + 2 < nch) cp_wait<2>();
        else if (c + 1 < nch) cp_wait<1>();
        else cp_wait<0>();
        __syncthreads();
        if (c + 3 < nch) { cp_tile((c + 3) * 64, (c + 3) & 3); cp_commit(); }

        u32 sA = sb + (c & 3) * STAGE_BYTES, sBB = sA + 16384;
        #pragma unroll
        for (int ks = 0; ks < 4; ks++) {
            u32 a[2][4], b[2][2];
            #pragma unroll
            for (int mi = 0; mi < 2; mi++) {
                int row = wm * 32 + mi * 16 + (lane & 15);
                int gq = ks * 2 + (lane >> 4);
                u32 ad = sA + SWZ(row * 128 + gq * 16);
                asm volatile("ldmatrix.sync.aligned.m8n8.x4.shared.b16 {%0,%1,%2,%3}, [%4];"
                             : "=r"(a[mi][0]), "=r"(a[mi][1]), "=r"(a[mi][2]), "=r"(a[mi][3]) : "r"(ad));
            }
            #pragma unroll
            for (int ni = 0; ni < 2; ni++) {
                int row = wn * 16 + ni * 8 + (lane & 7);
                int gq = ks * 2 + ((lane >> 3) & 1);
                u32 ad = sBB + SWZ(row * 128 + gq * 16);
                asm volatile("ldmatrix.sync.aligned.m8n8.x2.shared.b16 {%0,%1}, [%2];"
                             : "=r"(b[ni][0]), "=r"(b[ni][1]) : "r"(ad));
            }
            #pragma unroll
            for (int mi = 0; mi < 2; mi++)
                #pragma unroll
                for (int ni = 0; ni < 2; ni++)
                    asm volatile("mma.sync.aligned.m16n8k16.row.col.f32.bf16.bf16.f32 "
                                 "{%0,%1,%2,%3}, {%4,%5,%6,%7}, {%8,%9}, {%0,%1,%2,%3};"
                                 : "+f"(acc[mi][ni][0]), "+f"(acc[mi][ni][1]),
                                   "+f"(acc[mi][ni][2]), "+f"(acc[mi][ni][3])
                                 : "r"(a[mi][0]), "r"(a[mi][1]), "r"(a[mi][2]), "r"(a[mi][3]),
                                   "r"(b[ni][0]), "r"(b[ni][1]));
        }
        __syncthreads();
    }

    #pragma unroll
    for (int ni = 0; ni < 2; ni++) {
        int c0 = bn + wn * 16 + ni * 8 + (lane & 3) * 2;
        float b0 = bias[c0], b1 = bias[c0 + 1];
        #pragma unroll
        for (int mi = 0; mi < 2; mi++) {
            int r0 = bm + wm * 32 + mi * 16 + (lane >> 2);
            float v0 = acc[mi][ni][0] + b0, v1 = acc[mi][ni][1] + b1;
            float v2 = acc[mi][ni][2] + b0, v3 = acc[mi][ni][3] + b1;
            if (ACT == 1) { v0 = fmaxf(v0, 0.f); v1 = fmaxf(v1, 0.f); v2 = fmaxf(v2, 0.f); v3 = fmaxf(v3, 0.f); }
            if (ACT == 2) { v0 = tanhf(v0); v1 = tanhf(v1); v2 = tanhf(v2); v3 = tanhf(v3); }
            if (WF) {
                *(float2*)(Cf + (size_t)r0 * ldc + c0)       = make_float2(v0, v1);
                *(float2*)(Cf + (size_t)(r0 + 8) * ldc + c0) = make_float2(v2, v3);
            }
            if (WS) {
                __nv_bfloat16* s0 = Cs + (size_t)r0 * ldcs + c0;
                __nv_bfloat16* s1 = Cs + (size_t)(r0 + 8) * ldcs + c0;
                float vv[2][2] = {{v0, v1}, {v2, v3}};
                __nv_bfloat16* sp[2] = {s0, s1};
                #pragma unroll
                for (int rr = 0; rr < 2; rr++)
                    #pragma unroll
                    for (int jj = 0; jj < 2; jj++) {
                        float v = vv[rr][jj];
                        __nv_bfloat16 hi = __float2bfloat16(v);
                        __nv_bfloat16 lo = __float2bfloat16(v - __bfloat162float(hi));
                        sp[rr][jj] = hi; sp[rr][slotC + jj] = hi; sp[rr][2 * slotC + jj] = lo;
                    }
            }
        }
    }
}

// ---------------- neighborhood attention ----------------
__global__ void nbr_kernel() {
    int gwarp = (blockIdx.x * blockDim.x + threadIdx.x) >> 5;
    int lane = threadIdx.x & 31;
    if (gwarp >= NN) return;
    int i = gwarp;
    int r = i >> 6, c = i & 63;

    float hi[16];
    const float* Hi = g_H2 + (size_t)i * H2DIM;
    #pragma unroll
    for (int u = 0; u < 16; u++) hi[u] = Hi[lane + 32 * u];

    int nbrs[8]; int cnt = 0;
    for (int dr = -1; dr <= 1; dr++)
        for (int dc = -1; dc <= 1; dc++) {
            if (dr == 0 && dc == 0) continue;
            int rr = r + dr, cc = c + dc;
            if (rr >= 0 && rr < 32 && cc >= 0 && cc < 64) nbrs[cnt++] = rr * 64 + cc;
        }

    float dots[8];
    for (int q = 0; q < cnt; q++) {
        const float* An = g_An + (size_t)nbrs[q] * HDIM;
        float s = 0.f;
        #pragma unroll
        for (int u = 0; u < 16; u++) s += hi[u] * An[lane + 32 * u];
        #pragma unroll
        for (int o = 16; o; o >>= 1) s += __shfl_xor_sync(0xffffffffu, s, o);
        dots[q] = s;
    }
    float m = -3.0e38f;
    for (int q = 0; q < cnt; q++) m = fmaxf(m, dots[q]);
    float ssum = 0.f;
    for (int q = 0; q < cnt; q++) { dots[q] = expf(dots[q] - m); ssum += dots[q]; }
    float inv = 1.f / ssum;

    float accv[16];
    #pragma unroll
    for (int u = 0; u < 16; u++) accv[u] = 0.f;
    for (int q = 0; q < cnt; q++) {
        float a = dots[q] * inv;
        const float* Hj = g_H2 + (size_t)nbrs[q] * H2DIM;
        #pragma unroll
        for (int u = 0; u < 16; u++) accv[u] += a * Hj[lane + 32 * u];
    }
    float* o = g_H2 + (size_t)i * H2DIM + HDIM;
    __nv_bfloat16* os = g_H2s + (size_t)i * 3 * H2DIM;
    #pragma unroll
    for (int u = 0; u < 16; u++) {
        float v = accv[u];
        int col = 512 + lane + 32 * u;
        o[lane + 32 * u] = v;
        __nv_bfloat16 vh = __float2bfloat16(v);
        __nv_bfloat16 vl = __float2bfloat16(v - __bfloat162float(vh));
        os[col] = vh; os[1024 + col] = vh; os[2048 + col] = vl;
    }
}

// ---------------- template logits ----------------
__global__ void tlogits_kernel(const float* __restrict__ templates) {
    int n = blockIdx.x;
    int t = threadIdx.x >> 5, lane = threadIdx.x & 31;
    const float* p = g_P + (size_t)n * H2DIM;
    const float* tm = templates + (size_t)t * H2DIM;
    float s = 0.f;
    for (int k = lane; k < H2DIM; k += 32) s += p[k] * tm[k];
    #pragma unroll
    for (int o = 16; o; o >>= 1) s += __shfl_xor_sync(0xffffffffu, s, o);
    if (lane == 0) g_L[t * NN + n] = s;
}

// ---------------- betas softmax ----------------
__global__ void betas_kernel() {
    int t = blockIdx.x, tid = threadIdx.x;
    __shared__ float red[256];
    __shared__ float smax, ssum;
    const float* L = g_L + t * NN;
    float m = -3.0e38f;
    for (int n = tid; n < NN; n += 256) m = fmaxf(m, L[n]);
    red[tid] = m; __syncthreads();
    for (int s = 128; s; s >>= 1) { if (tid < s) red[tid] = fmaxf(red[tid], red[tid + s]); __syncthreads(); }
    if (tid == 0) smax = red[0];
    __syncthreads();
    float acc = 0.f;
    for (int n = tid; n < NN; n += 256) acc += expf(L[n] - smax);
    red[tid] = acc; __syncthreads();
    for (int s = 128; s; s >>= 1) { if (tid < s) red[tid] += red[tid + s]; __syncthreads(); }
    if (tid == 0) ssum = 1.f / red[0];
    __syncthreads();
    for (int n = tid; n < NN; n += 256)
        g_betas[t * NN + n] = expf(L[n] - smax) * ssum;
}

// ---------------- embs partials ----------------
__global__ void embs_part_kernel() {
    __shared__ float bsh[TDIM * 128];
    int col = blockIdx.x * 128 + threadIdx.x;
    int s = blockIdx.y;
    int n0 = s * 128;
    for (int i = threadIdx.x; i < TDIM * 128; i += 128) {
        int t = i >> 7, nl = i & 127;
        bsh[i] = g_betas[t * NN + n0 + nl];
    }
    __syncthreads();
    float acc[TDIM];
    #pragma unroll
    for (int t = 0; t < TDIM; t++) acc[t] = 0.f;
    for (int nl = 0; nl < 128; nl++) {
        float h = g_H2[(size_t)(n0 + nl) * H2DIM + col];
        #pragma unroll
        for (int t = 0; t < TDIM; t++) acc[t] += bsh[t * 128 + nl] * h;
    }
    #pragma unroll
    for (int t = 0; t < TDIM; t++)
        g_embs_part[(size_t)(s * TDIM + t) * H2DIM + col] = acc[t];
}

__global__ void embs_reduce_kernel() {
    int i = blockIdx.x * 256 + threadIdx.x;
    if (i >= TDIM * H2DIM) return;
    float s = 0.f;
    #pragma unroll
    for (int p = 0; p < NSPLIT; p++) s += g_embs_part[(size_t)p * TDIM * H2DIM + i];
    g_embs[i] = s;
}

// ---------------- glob1 ----------------
__global__ void glob1_kernel(const float* __restrict__ glob_w1, const float* __restrict__ glob_b1) {
    int t = blockIdx.y;
    int w = threadIdx.x >> 5, lane = threadIdx.x & 31;
    int j = blockIdx.x * 8 + w;
    const float* wr = glob_w1 + (size_t)j * H2DIM;
    const float* e = g_embs + t * H2DIM;
    float s = 0.f;
    #pragma unroll 8
    for (int k = lane; k < H2DIM; k += 32) s += wr[k] * e[k];
    #pragma unroll
    for (int o = 16; o; o >>= 1) s += __shfl_xor_sync(0xffffffffu, s, o);
    if (lane == 0) g_V[t * 128 + j] = tanhf(s + glob_b1[j]);
}

// ---------------- final2 ----------------
__global__ void final2_kernel(const float* __restrict__ glob_w2, const float* __restrict__ glob_b2,
                              const float* __restrict__ cls_w,  const float* __restrict__ cls_b,
                              float* __restrict__ out, int out_size) {
    __shared__ float vsh[TDIM * 128];
    __shared__ float Msh[H2DIM];
    __shared__ float gam[TDIM];
    __shared__ float psh[2];
    int tid = threadIdx.x;

    for (int i = tid; i < TDIM * 128; i += 256) vsh[i] = g_V[i];
    __syncthreads();

    if (tid < TDIM) {
        float s = glob_b2[0];
        for (int j = 0; j < 128; j++) s += glob_w2[j] * vsh[tid * 128 + j];
        gam[tid] = s;
    }
    __syncthreads();
    if (tid == 0) {
        float m = gam[0];
        for (int t = 1; t < TDIM; t++) m = fmaxf(m, gam[t]);
        float ss = 0.f;
        for (int t = 0; t < TDIM; t++) { gam[t] = expf(gam[t] - m); ss += gam[t]; }
        float inv = 1.f / ss;
        for (int t = 0; t < TDIM; t++) gam[t] *= inv;
    }
    __syncthreads();

    for (int k = tid; k < H2DIM; k += 256) {
        float s = 0.f;
        #pragma unroll
        for (int t = 0; t < TDIM; t++) s += gam[t] * g_embs[t * H2DIM + k];
        Msh[k] = s;
    }
    __syncthreads();

    if (tid < 64) {
        int c = tid >> 5, lane = tid & 31;
        float s = 0.f;
        for (int k = lane; k < H2DIM; k += 32) s += cls_w[(size_t)c * H2DIM + k] * Msh[k];
        #pragma unroll
        for (int o = 16; o; o >>= 1) s += __shfl_xor_sync(0xffffffffu, s, o);
        if (lane == 0) {
            float p = 1.f / (1.f + expf(-(s + cls_b[c])));
            psh[c] = p;
            if (c < out_size) out[c] = p;
        }
    }
    __syncthreads();
    if (tid == 0 && out_size > 2) out[2] = (psh[1] > psh[0]) ? 1.0f : 0.0f;

    for (int n = tid; n < NN; n += 256) {
        float s = 0.f;
        #pragma unroll
        for (int t = 0; t < TDIM; t++) s += gam[t] * g_betas[t * NN + n];
        if (3 + n < out_size) out[3 + n] = s;
    }
}

// ---------------- launch ----------------
extern "C" void kernel_launch(void* const* d_in, const int* in_sizes, int n_in,
                              void* d_out, int out_size) {
    const float* x        = (const float*)d_in[0];
    const float* conv1_w  = (const float*)d_in[2];
    const float* conv1_b  = (const float*)d_in[3];
    const float* conv2_w  = (const float*)d_in[4];
    const float* conv2_b  = (const float*)d_in[5];
    const float* fc1_w    = (const float*)d_in[6];
    const float* fc1_b    = (const float*)d_in[7];
    const float* fc2_w    = (const float*)d_in[8];
    const float* fc2_b    = (const float*)d_in[9];
    const float* nbr_w    = (const float*)d_in[10];
    const float* nbr_b    = (const float*)d_in[11];
    const float* templates= (const float*)d_in[12];
    const float* proto_w  = (const float*)d_in[13];
    const float* proto_b  = (const float*)d_in[14];
    const float* glob_w1  = (const float*)d_in[15];
    const float* glob_b1  = (const float*)d_in[16];
    const float* glob_w2  = (const float*)d_in[17];
    const float* glob_b2  = (const float*)d_in[18];
    const float* cls_w    = (const float*)d_in[19];
    const float* cls_b    = (const float*)d_in[20];
    float* out = (float*)d_out;

    float *H2, *An, *P;
    __nv_bfloat16 *H0s, *H1s, *H2s, *fc1ws, *fc2ws, *nbrws, *protows;
    cudaGetSymbolAddress((void**)&H2, g_H2);
    cudaGetSymbolAddress((void**)&An, g_An);
    cudaGetSymbolAddress((void**)&P,  g_P);
    cudaGetSymbolAddress((void**)&H0s, g_H0s);
    cudaGetSymbolAddress((void**)&H1s, g_H1s);
    cudaGetSymbolAddress((void**)&H2s, g_H2s);
    cudaGetSymbolAddress((void**)&fc1ws, g_fc1ws);
    cudaGetSymbolAddress((void**)&fc2ws, g_fc2ws);
    cudaGetSymbolAddress((void**)&nbrws, g_nbrws);
    cudaGetSymbolAddress((void**)&protows, g_protows);

    const size_t conv_smem = S_TOTALF * sizeof(float);
    cudaFuncSetAttribute(conv_fused_kernel, cudaFuncAttributeMaxDynamicSharedMemorySize, (int)conv_smem);
    const int gsmem = 4 * STAGE_BYTES;   // 98304
    cudaFuncSetAttribute(mma_gemm<1, false, true>,  cudaFuncAttributeMaxDynamicSharedMemorySize, gsmem);
    cudaFuncSetAttribute(mma_gemm<1, true,  true>,  cudaFuncAttributeMaxDynamicSharedMemorySize, gsmem);
    cudaFuncSetAttribute(mma_gemm<2, true,  false>, cudaFuncAttributeMaxDynamicSharedMemorySize, gsmem);

    // 1 noop: capture = 4th launch -> fc1 mma_gemm (A/B the 16-warp config)
    noop_kernel<<<1, 32>>>();

    conv_fused_kernel<<<NN, 512, conv_smem>>>(x, conv1_w, conv1_b, conv2_w, conv2_b);

    const int cvt_total = CVT_N1 + CVT_N2 + CVT_N3 + CVT_N4;
    cvt_all_kernel<<<(cvt_total + 255) / 256, 256>>>(fc1_w, fc2_w, nbr_w, proto_w);

    mma_gemm<1, false, true><<<dim3(HDIM / 64, NN / 128), 512, gsmem>>>(
        H0s, fc1ws, fc1_b, nullptr, H1s, H0DIM, 3 * H0DIM, H0DIM, 3 * H0DIM, H0DIM, 0, 3 * HDIM, HDIM);
    mma_gemm<1, true, true><<<dim3(HDIM / 64, NN / 128), 512, gsmem>>>(
        H1s, fc2ws, fc2_b, H2, H2s, HDIM, 3 * HDIM, HDIM, 3 * HDIM, HDIM, H2DIM, 3 * H2DIM, H2DIM);
    mma_gemm<2, true, false><<<dim3(HDIM / 64, NN / 128), 512, gsmem>>>(
        H2s, nbrws, nbr_b, An, nullptr, HDIM, 3 * H2DIM, H2DIM, 3 * HDIM, HDIM, HDIM, 0, 0);
    nbr_kernel<<<NN / 8, 256>>>();
    mma_gemm<2, true, false><<<dim3(H2DIM / 64, NN / 128), 512, gsmem>>>(
        H2s, protows, proto_b, P, nullptr, H2DIM, 3 * H2DIM, H2DIM, 3 * H2DIM, H2DIM, H2DIM, 0, 0);

    tlogits_kernel<<<NN, 320>>>(templates);
    betas_kernel<<<TDIM, 256>>>();
    embs_part_kernel<<<dim3(H2DIM / 128, NSPLIT), 128>>>();
    embs_reduce_kernel<<<(TDIM * H2DIM + 255) / 256, 256>>>();
    glob1_kernel<<<dim3(16, TDIM), 256>>>(glob_w1, glob_b1);
    final2_kernel<<<1, 256>>>(glob_w2, glob_b2, cls_w, cls_b, out, out_size);
}

// round 15
// speedup vs baseline: 1.0440x; 1.0440x over previous
#include <cuda_runtime.h>
#include <cuda_bf16.h>
#include <math.h>

typedef unsigned long long ull;
typedef unsigned int u32;

// ---------------- problem constants ----------------
#define NN        2048
#define P1        14
#define H0DIM     1728
#define HDIM      512
#define H2DIM     1024
#define TDIM      10
#define NSPLIT    16

// conv SMEM layout (floats)
#define S_IMG     0
#define S_W1      1056
#define S_B1      1632
#define S_B2      1668
#define S_POOL1   1716
#define S_W2      8772
#define W2STRIDE  50
#define S_TOTALF  (8772 + 16200)

#define SWZ(off)  ((off) ^ (((off) >> 3) & 0x70))

// ---------------- scratch ----------------
__device__ float g_H2[(size_t)NN * H2DIM];
__device__ float g_An[(size_t)NN * HDIM];
__device__ float g_P[(size_t)NN * H2DIM];
__device__ float g_L[TDIM * NN];
__device__ float g_betas[TDIM * NN];
__device__ float g_embs_part[NSPLIT * TDIM * H2DIM];
__device__ float g_embs[TDIM * H2DIM];
__device__ float g_V[TDIM * 128];

__device__ __align__(256) __nv_bfloat16 g_H0s[(size_t)NN * 3 * H0DIM];
__device__ __align__(256) __nv_bfloat16 g_H1s[(size_t)NN * 3 * HDIM];
__device__ __align__(256) __nv_bfloat16 g_H2s[(size_t)NN * 3 * H2DIM];
__device__ __align__(256) __nv_bfloat16 g_fc1ws[(size_t)HDIM * 3 * H0DIM];
__device__ __align__(256) __nv_bfloat16 g_fc2ws[(size_t)HDIM * 3 * HDIM];
__device__ __align__(256) __nv_bfloat16 g_nbrws[(size_t)HDIM * 3 * HDIM];
__device__ __align__(256) __nv_bfloat16 g_protows[(size_t)H2DIM * 3 * H2DIM];

__device__ __forceinline__ u32 smem_u32(const void* p) {
    u32 a; asm("{ .reg .u64 t; cvta.to.shared.u64 t, %1; cvt.u32.u64 %0, t; }" : "=r"(a) : "l"(p));
    return a;
}
__device__ __forceinline__ void cp16(u32 dst, const void* src) {
    asm volatile("cp.async.ca.shared.global [%0], [%1], 16;" :: "r"(dst), "l"(src));
}
__device__ __forceinline__ void cp_commit() { asm volatile("cp.async.commit_group;" ::: "memory"); }
template <int N>
__device__ __forceinline__ void cp_wait() { asm volatile("cp.async.wait_group %0;" :: "n"(N) : "memory"); }

// ---------------- merged weight split cvt ----------------
#define CVT_N1 884736
#define CVT_N2 262144
#define CVT_N3 262144
#define CVT_N4 1048576
__global__ void cvt_all_kernel(const float* __restrict__ w1m, const float* __restrict__ w2m,
                               const float* __restrict__ w3m, const float* __restrict__ w4m) {
    int idx = blockIdx.x * 256 + threadIdx.x;
    const float* w; __nv_bfloat16* o; int K; int li;
    if (idx < CVT_N1) { w = w1m; o = g_fc1ws; K = H0DIM; li = idx; }
    else if (idx < CVT_N1 + CVT_N2) { w = w2m; o = g_fc2ws; K = HDIM; li = idx - CVT_N1; }
    else if (idx < CVT_N1 + CVT_N2 + CVT_N3) { w = w3m; o = g_nbrws; K = HDIM; li = idx - CVT_N1 - CVT_N2; }
    else if (idx < CVT_N1 + CVT_N2 + CVT_N3 + CVT_N4) { w = w4m; o = g_protows; K = H2DIM; li = idx - CVT_N1 - CVT_N2 - CVT_N3; }
    else return;
    int n = li / K, k = li - n * K;
    float v = w[li];
    __nv_bfloat16 hi = __float2bfloat16(v);
    __nv_bfloat16 lo = __float2bfloat16(v - __bfloat162float(hi));
    size_t base = (size_t)n * 3 * K + k;
    o[base] = hi; o[base + K] = lo; o[base + 2 * K] = hi;
}

// ---------------- fused conv (R7/R10-proven config) ----------------
__device__ __forceinline__ ull pack2(float lo, float hi) {
    ull r; asm("mov.b64 %0, {%1, %2};" : "=l"(r) : "f"(lo), "f"(hi)); return r;
}
__device__ __forceinline__ void unpack2(ull v, float& lo, float& hi) {
    asm("mov.b64 {%0, %1}, %2;" : "=f"(lo), "=f"(hi) : "l"(v));
}
__device__ __forceinline__ void fma2(ull& d, ull a, ull b) {
    asm("fma.rn.f32x2 %0, %1, %2, %0;" : "+l"(d) : "l"(a), "l"(b));
}

__global__ __launch_bounds__(512, 2)
void conv_fused_kernel(const float* __restrict__ x,
                       const float* __restrict__ w1,
                       const float* __restrict__ b1,
                       const float* __restrict__ w2,
                       const float* __restrict__ b2) {
    extern __shared__ float sm[];
    float* s_img   = sm + S_IMG;
    float* s_w1    = sm + S_W1;
    float* s_b1    = sm + S_B1;
    float* s_b2    = sm + S_B2;
    float* s_pool1 = sm + S_POOL1;
    float* s_w2    = sm + S_W2;

    int n = blockIdx.x, tid = threadIdx.x;
    const float* xin = x + (size_t)n * 1024;

    for (int i = tid; i < 1024; i += 512) {
        int r = i >> 5, c = i & 31;
        s_img[r * 33 + c] = xin[i];
    }
    for (int i = tid; i < 576; i += 512) s_w1[i] = w1[i];
    if (tid < 36) s_b1[tid] = b1[tid];
    else if (tid >= 64 && tid < 112) s_b2[tid - 64] = b2[tid - 64];
    for (int i = tid; i < 15552; i += 512) {
        int ch = i / 324, r = i - ch * 324;
        s_w2[r * W2STRIDE + ch] = w2[i];
    }
    __syncthreads();

    if (tid < 504) {
        int ch = tid / 14, py = tid % 14;
        const float4* wp = (const float4*)&s_w1[ch * 16];
        float4 a0 = wp[0], a1 = wp[1], a2 = wp[2], a3 = wp[3];
        float wr[16] = {a0.x,a0.y,a0.z,a0.w, a1.x,a1.y,a1.z,a1.w,
                        a2.x,a2.y,a2.z,a2.w, a3.x,a3.y,a3.z,a3.w};
        float bias1 = s_b1[ch];
        float* prow = s_pool1 + ch * 196 + py * 14;
        const float* ibase = s_img + (2 * py) * 33;
        for (int px = 0; px < 14; px++) {
            float s00 = 0.f, s01 = 0.f, s10 = 0.f, s11 = 0.f;
            const float* ip = ibase + 2 * px;
            #pragma unroll
            for (int yy = 0; yy < 5; yy++) {
                float r0 = ip[yy * 33 + 0], r1 = ip[yy * 33 + 1], r2 = ip[yy * 33 + 2];
                float r3 = ip[yy * 33 + 3], r4 = ip[yy * 33 + 4];
                if (yy <= 3) {
                    const float* w = wr + yy * 4;
                    s00 += r0 * w[0] + r1 * w[1] + r2 * w[2] + r3 * w[3];
                    s01 += r1 * w[0] + r2 * w[1] + r3 * w[2] + r4 * w[3];
                }
                if (yy >= 1) {
                    const float* w = wr + (yy - 1) * 4;
                    s10 += r0 * w[0] + r1 * w[1] + r2 * w[2] + r3 * w[3];
                    s11 += r1 * w[0] + r2 * w[1] + r3 * w[2] + r4 * w[3];
                }
            }
            float m = fmaxf(fmaxf(s00, s01), fmaxf(s10, s11));
            prow[px] = fmaxf(m + bias1, 0.f);
        }
    }
    __syncthreads();

    // conv2: thread = (16-ch group g, position pair q/q+72)
    ull acc0[8], acc1[8];
    int g = tid / 72, q = tid - g * 72;
    if (tid < 216) {
        int cy = q / 12, cx = q - cy * 12;
        #pragma unroll
        for (int j = 0; j < 8; j++) { acc0[j] = 0ull; acc1[j] = 0ull; }
        const float* in0 = s_pool1 + cy * 14 + cx;
        const float* in1 = in0 + 84;
        const float* wgb = s_w2 + g * 16;
        for (int c = 0; c < 36; c++) {
            #pragma unroll
            for (int k = 0; k < 9; k++) {
                int ioff = c * 196 + (k / 3) * 14 + (k % 3);
                float v0 = in0[ioff], v1 = in1[ioff];
                ull vv0 = pack2(v0, v0), vv1 = pack2(v1, v1);
                const ull* qw = (const ull*)(wgb + (c * 9 + k) * W2STRIDE);
                #pragma unroll
                for (int j = 0; j < 8; j++) {
                    ull w = qw[j];
                    fma2(acc0[j], w, vv0);
                    fma2(acc1[j], w, vv1);
                }
            }
        }
    }
    __syncthreads();
    if (tid < 216) {
        float* o0 = s_w2 + q * 49 + g * 16;
        float* o1 = s_w2 + (q + 72) * 49 + g * 16;
        #pragma unroll
        for (int j = 0; j < 8; j++) {
            float lo, hi;
            unpack2(acc0[j], lo, hi); o0[2 * j] = lo; o0[2 * j + 1] = hi;
            unpack2(acc1[j], lo, hi); o1[2 * j] = lo; o1[2 * j + 1] = hi;
        }
    }
    __syncthreads();

    __nv_bfloat16* outb = g_H0s + (size_t)n * 3 * H0DIM;
    for (int o = tid; o < 1728; o += 512) {
        int ch = o / 36, pp = o - ch * 36;
        int py = pp / 6, px = pp - py * 6;
        int i00 = (2 * py) * 12 + 2 * px;
        float m = fmaxf(fmaxf(s_w2[i00 * 49 + ch],        s_w2[(i00 + 1)  * 49 + ch]),
                        fmaxf(s_w2[(i00 + 12) * 49 + ch], s_w2[(i00 + 13) * 49 + ch]));
        float v = fmaxf(m + s_b2[ch], 0.f);
        __nv_bfloat16 hi = __float2bfloat16(v);
        __nv_bfloat16 lo = __float2bfloat16(v - __bfloat162float(hi));
        outb[o] = hi; outb[1728 + o] = hi; outb[3456 + o] = lo;
    }
}

// ---------------- mma.sync bf16 GEMM 128x64, 8 warps, 4-stage, B via x4 -------
#define STAGE_BYTES 24576
template <int ACT, bool WF, bool WS>
__global__ __launch_bounds__(256)
void mma_gemm(const __nv_bfloat16* __restrict__ A, const __nv_bfloat16* __restrict__ B,
              const float* __restrict__ bias, float* __restrict__ Cf, __nv_bfloat16* __restrict__ Cs,
              int K, int rsA, int ssA, int rsB, int ssB, int ldc, int ldcs, int slotC) {
    extern __shared__ char smem[];
    u32 sb = smem_u32(smem);
    const int tid = threadIdx.x, wid = tid >> 5, lane = tid & 31;
    const int bm = blockIdx.y * 128, bn = blockIdx.x * 64;
    const int wm = wid & 1, wn = wid >> 1;
    const int lr = tid >> 3, lg = tid & 7;

    auto cp_tile = [&](int kc, int buf) {   // kc in elements (multiple of 64)
        int slot = kc / K, off = kc - slot * K;
        u32 base = sb + buf * STAGE_BYTES;
        const __nv_bfloat16* Ab = A + (size_t)bm * rsA + (size_t)slot * ssA + off;
        #pragma unroll
        for (int i = 0; i < 4; i++)
            cp16(base + SWZ((lr + i * 32) * 128 + lg * 16), Ab + (size_t)(lr + i * 32) * rsA + lg * 8);
        const __nv_bfloat16* Bb = B + (size_t)bn * rsB + (size_t)slot * ssB + off;
        #pragma unroll
        for (int i = 0; i < 2; i++)
            cp16(base + 16384 + SWZ((lr + i * 32) * 128 + lg * 16), Bb + (size_t)(lr + i * 32) * rsB + lg * 8);
    };

    float acc[4][2][4];
    #pragma unroll
    for (int mi = 0; mi < 4; mi++)
        #pragma unroll
        for (int ni = 0; ni < 2; ni++)
            #pragma unroll
            for (int j = 0; j < 4; j++) acc[mi][ni][j] = 0.f;

    const int nch = (3 * K) / 64;
    cp_tile(0, 0); cp_commit();
    cp_tile(64, 1); cp_commit();
    cp_tile(128, 2); cp_commit();

    for (int c = 0; c < nch; c++) {
        if (c + 2 < nch) cp_wait<2>();
        else if (c + 1 < nch) cp_wait<1>();
        else cp_wait<0>();
        __syncthreads();
        if (c + 3 < nch) { cp_tile((c + 3) * 64, (c + 3) & 3); cp_commit(); }

        u32 sA = sb + (c & 3) * STAGE_BYTES, sBB = sA + 16384;
        #pragma unroll
        for (int ks = 0; ks < 4; ks++) {
            u32 a[4][4], b[4];
            #pragma unroll
            for (int mi = 0; mi < 4; mi++) {
                int row = wm * 64 + mi * 16 + (lane & 15);
                int gq = ks * 2 + (lane >> 4);
                u32 ad = sA + SWZ(row * 128 + gq * 16);
                asm volatile("ldmatrix.sync.aligned.m8n8.x4.shared.b16 {%0,%1,%2,%3}, [%4];"
                             : "=r"(a[mi][0]), "=r"(a[mi][1]), "=r"(a[mi][2]), "=r"(a[mi][3]) : "r"(ad));
            }
            {
                // one x4 loads BOTH ni fragments:
                // lanes 0-7:  rows wn*16+0..7,  gq = ks*2
                // lanes 8-15: rows wn*16+0..7,  gq = ks*2+1
                // lanes 16-23:rows wn*16+8..15, gq = ks*2
                // lanes 24-31:rows wn*16+8..15, gq = ks*2+1
                int row = wn * 16 + ((lane >> 4) & 1) * 8 + (lane & 7);
                int gq = ks * 2 + ((lane >> 3) & 1);
                u32 ad = sBB + SWZ(row * 128 + gq * 16);
                asm volatile("ldmatrix.sync.aligned.m8n8.x4.shared.b16 {%0,%1,%2,%3}, [%4];"
                             : "=r"(b[0]), "=r"(b[1]), "=r"(b[2]), "=r"(b[3]) : "r"(ad));
            }
            #pragma unroll
            for (int mi = 0; mi < 4; mi++) {
                asm volatile("mma.sync.aligned.m16n8k16.row.col.f32.bf16.bf16.f32 "
                             "{%0,%1,%2,%3}, {%4,%5,%6,%7}, {%8,%9}, {%0,%1,%2,%3};"
                             : "+f"(acc[mi][0][0]), "+f"(acc[mi][0][1]), "+f"(acc[mi][0][2]), "+f"(acc[mi][0][3])
                             : "r"(a[mi][0]), "r"(a[mi][1]), "r"(a[mi][2]), "r"(a[mi][3]),
                               "r"(b[0]), "r"(b[1]));
                asm volatile("mma.sync.aligned.m16n8k16.row.col.f32.bf16.bf16.f32 "
                             "{%0,%1,%2,%3}, {%4,%5,%6,%7}, {%8,%9}, {%0,%1,%2,%3};"
                             : "+f"(acc[mi][1][0]), "+f"(acc[mi][1][1]), "+f"(acc[mi][1][2]), "+f"(acc[mi][1][3])
                             : "r"(a[mi][0]), "r"(a[mi][1]), "r"(a[mi][2]), "r"(a[mi][3]),
                               "r"(b[2]), "r"(b[3]));
            }
        }
        __syncthreads();
    }

    #pragma unroll
    for (int ni = 0; ni < 2; ni++) {
        int c0 = bn + wn * 16 + ni * 8 + (lane & 3) * 2;
        float b0 = bias[c0], b1 = bias[c0 + 1];
        #pragma unroll
        for (int mi = 0; mi < 4; mi++) {
            int r0 = bm + wm * 64 + mi * 16 + (lane >> 2);
            float v0 = acc[mi][ni][0] + b0, v1 = acc[mi][ni][1] + b1;
            float v2 = acc[mi][ni][2] + b0, v3 = acc[mi][ni][3] + b1;
            if (ACT == 1) { v0 = fmaxf(v0, 0.f); v1 = fmaxf(v1, 0.f); v2 = fmaxf(v2, 0.f); v3 = fmaxf(v3, 0.f); }
            if (ACT == 2) { v0 = tanhf(v0); v1 = tanhf(v1); v2 = tanhf(v2); v3 = tanhf(v3); }
            if (WF) {
                *(float2*)(Cf + (size_t)r0 * ldc + c0)       = make_float2(v0, v1);
                *(float2*)(Cf + (size_t)(r0 + 8) * ldc + c0) = make_float2(v2, v3);
            }
            if (WS) {
                __nv_bfloat16* s0 = Cs + (size_t)r0 * ldcs + c0;
                __nv_bfloat16* s1 = Cs + (size_t)(r0 + 8) * ldcs + c0;
                float vv[2][2] = {{v0, v1}, {v2, v3}};
                __nv_bfloat16* sp[2] = {s0, s1};
                #pragma unroll
                for (int rr = 0; rr < 2; rr++)
                    #pragma unroll
                    for (int jj = 0; jj < 2; jj++) {
                        float v = vv[rr][jj];
                        __nv_bfloat16 hi = __float2bfloat16(v);
                        __nv_bfloat16 lo = __float2bfloat16(v - __bfloat162float(hi));
                        sp[rr][jj] = hi; sp[rr][slotC + jj] = hi; sp[rr][2 * slotC + jj] = lo;
                    }
            }
        }
    }
}

// ---------------- neighborhood attention ----------------
__global__ void nbr_kernel() {
    int gwarp = (blockIdx.x * blockDim.x + threadIdx.x) >> 5;
    int lane = threadIdx.x & 31;
    if (gwarp >= NN) return;
    int i = gwarp;
    int r = i >> 6, c = i & 63;

    float hi[16];
    const float* Hi = g_H2 + (size_t)i * H2DIM;
    #pragma unroll
    for (int u = 0; u < 16; u++) hi[u] = Hi[lane + 32 * u];

    int nbrs[8]; int cnt = 0;
    for (int dr = -1; dr <= 1; dr++)
        for (int dc = -1; dc <= 1; dc++) {
            if (dr == 0 && dc == 0) continue;
            int rr = r + dr, cc = c + dc;
            if (rr >= 0 && rr < 32 && cc >= 0 && cc < 64) nbrs[cnt++] = rr * 64 + cc;
        }

    float dots[8];
    for (int q = 0; q < cnt; q++) {
        const float* An = g_An + (size_t)nbrs[q] * HDIM;
        float s = 0.f;
        #pragma unroll
        for (int u = 0; u < 16; u++) s += hi[u] * An[lane + 32 * u];
        #pragma unroll
        for (int o = 16; o; o >>= 1) s += __shfl_xor_sync(0xffffffffu, s, o);
        dots[q] = s;
    }
    float m = -3.0e38f;
    for (int q = 0; q < cnt; q++) m = fmaxf(m, dots[q]);
    float ssum = 0.f;
    for (int q = 0; q < cnt; q++) { dots[q] = expf(dots[q] - m); ssum += dots[q]; }
    float inv = 1.f / ssum;

    float accv[16];
    #pragma unroll
    for (int u = 0; u < 16; u++) accv[u] = 0.f;
    for (int q = 0; q < cnt; q++) {
        float a = dots[q] * inv;
        const float* Hj = g_H2 + (size_t)nbrs[q] * H2DIM;
        #pragma unroll
        for (int u = 0; u < 16; u++) accv[u] += a * Hj[lane + 32 * u];
    }
    float* o = g_H2 + (size_t)i * H2DIM + HDIM;
    __nv_bfloat16* os = g_H2s + (size_t)i * 3 * H2DIM;
    #pragma unroll
    for (int u = 0; u < 16; u++) {
        float v = accv[u];
        int col = 512 + lane + 32 * u;
        o[lane + 32 * u] = v;
        __nv_bfloat16 vh = __float2bfloat16(v);
        __nv_bfloat16 vl = __float2bfloat16(v - __bfloat162float(vh));
        os[col] = vh; os[1024 + col] = vh; os[2048 + col] = vl;
    }
}

// ---------------- template logits (SMEM row cache) ----------------
__global__ void tlogits_kernel(const float* __restrict__ templates) {
    __shared__ float prow[H2DIM];
    int n = blockIdx.x, tid = threadIdx.x;  // 256
    const float* p = g_P + (size_t)n * H2DIM;
    for (int i = tid; i < H2DIM; i += 256) prow[i] = p[i];
    __syncthreads();
    int w = tid >> 5, lane = tid & 31;
    for (int t = w; t < TDIM; t += 8) {
        const float* tm = templates + (size_t)t * H2DIM;
        float s = 0.f;
        #pragma unroll 8
        for (int k = lane; k < H2DIM; k += 32) s += prow[k] * tm[k];
        #pragma unroll
        for (int o = 16; o; o >>= 1) s += __shfl_xor_sync(0xffffffffu, s, o);
        if (lane == 0) g_L[t * NN + n] = s;
    }
}

// ---------------- betas softmax ----------------
__global__ void betas_kernel() {
    int t = blockIdx.x, tid = threadIdx.x;
    __shared__ float red[256];
    __shared__ float smax, ssum;
    const float* L = g_L + t * NN;
    float m = -3.0e38f;
    for (int n = tid; n < NN; n += 256) m = fmaxf(m, L[n]);
    red[tid] = m; __syncthreads();
    for (int s = 128; s; s >>= 1) { if (tid < s) red[tid] = fmaxf(red[tid], red[tid + s]); __syncthreads(); }
    if (tid == 0) smax = red[0];
    __syncthreads();
    float acc = 0.f;
    for (int n = tid; n < NN; n += 256) acc += expf(L[n] - smax);
    red[tid] = acc; __syncthreads();
    for (int s = 128; s; s >>= 1) { if (tid < s) red[tid] += red[tid + s]; __syncthreads(); }
    if (tid == 0) ssum = 1.f / red[0];
    __syncthreads();
    for (int n = tid; n < NN; n += 256)
        g_betas[t * NN + n] = expf(L[n] - smax) * ssum;
}

// ---------------- embs partials ----------------
__global__ void embs_part_kernel() {
    __shared__ float bsh[TDIM * 128];
    int col = blockIdx.x * 128 + threadIdx.x;
    int s = blockIdx.y;
    int n0 = s * 128;
    for (int i = threadIdx.x; i < TDIM * 128; i += 128) {
        int t = i >> 7, nl = i & 127;
        bsh[i] = g_betas[t * NN + n0 + nl];
    }
    __syncthreads();
    float acc[TDIM];
    #pragma unroll
    for (int t = 0; t < TDIM; t++) acc[t] = 0.f;
    for (int nl = 0; nl < 128; nl++) {
        float h = g_H2[(size_t)(n0 + nl) * H2DIM + col];
        #pragma unroll
        for (int t = 0; t < TDIM; t++) acc[t] += bsh[t * 128 + nl] * h;
    }
    #pragma unroll
    for (int t = 0; t < TDIM; t++)
        g_embs_part[(size_t)(s * TDIM + t) * H2DIM + col] = acc[t];
}

__global__ void embs_reduce_kernel() {
    int i = blockIdx.x * 256 + threadIdx.x;
    if (i >= TDIM * H2DIM) return;
    float s = 0.f;
    #pragma unroll
    for (int p = 0; p < NSPLIT; p++) s += g_embs_part[(size_t)p * TDIM * H2DIM + i];
    g_embs[i] = s;
}

// ---------------- glob1 ----------------
__global__ void glob1_kernel(const float* __restrict__ glob_w1, const float* __restrict__ glob_b1) {
    int t = blockIdx.y;
    int w = threadIdx.x >> 5, lane = threadIdx.x & 31;
    int j = blockIdx.x * 8 + w;
    const float* wr = glob_w1 + (size_t)j * H2DIM;
    const float* e = g_embs + t * H2DIM;
    float s = 0.f;
    #pragma unroll 8
    for (int k = lane; k < H2DIM; k += 32) s += wr[k] * e[k];
    #pragma unroll
    for (int o = 16; o; o >>= 1) s += __shfl_xor_sync(0xffffffffu, s, o);
    if (lane == 0) g_V[t * 128 + j] = tanhf(s + glob_b1[j]);
}

// ---------------- final2 ----------------
__global__ void final2_kernel(const float* __restrict__ glob_w2, const float* __restrict__ glob_b2,
                              const float* __restrict__ cls_w,  const float* __restrict__ cls_b,
                              float* __restrict__ out, int out_size) {
    __shared__ float vsh[TDIM * 128];
    __shared__ float Msh[H2DIM];
    __shared__ float gam[TDIM];
    __shared__ float psh[2];
    int tid = threadIdx.x;

    for (int i = tid; i < TDIM * 128; i += 256) vsh[i] = g_V[i];
    __syncthreads();

    if (tid < TDIM) {
        float s = glob_b2[0];
        for (int j = 0; j < 128; j++) s += glob_w2[j] * vsh[tid * 128 + j];
        gam[tid] = s;
    }
    __syncthreads();
    if (tid == 0) {
        float m = gam[0];
        for (int t = 1; t < TDIM; t++) m = fmaxf(m, gam[t]);
        float ss = 0.f;
        for (int t = 0; t < TDIM; t++) { gam[t] = expf(gam[t] - m); ss += gam[t]; }
        float inv = 1.f / ss;
        for (int t = 0; t < TDIM; t++) gam[t] *= inv;
    }
    __syncthreads();

    for (int k = tid; k < H2DIM; k += 256) {
        float s = 0.f;
        #pragma unroll
        for (int t = 0; t < TDIM; t++) s += gam[t] * g_embs[t * H2DIM + k];
        Msh[k] = s;
    }
    __syncthreads();

    if (tid < 64) {
        int c = tid >> 5, lane = tid & 31;
        float s = 0.f;
        for (int k = lane; k < H2DIM; k += 32) s += cls_w[(size_t)c * H2DIM + k] * Msh[k];
        #pragma unroll
        for (int o = 16; o; o >>= 1) s += __shfl_xor_sync(0xffffffffu, s, o);
        if (lane == 0) {
            float p = 1.f / (1.f + expf(-(s + cls_b[c])));
            psh[c] = p;
            if (c < out_size) out[c] = p;
        }
    }
    __syncthreads();
    if (tid == 0 && out_size > 2) out[2] = (psh[1] > psh[0]) ? 1.0f : 0.0f;

    for (int n = tid; n < NN; n += 256) {
        float s = 0.f;
        #pragma unroll
        for (int t = 0; t < TDIM; t++) s += gam[t] * g_betas[t * NN + n];
        if (3 + n < out_size) out[3 + n] = s;
    }
}

// ---------------- launch ----------------
extern "C" void kernel_launch(void* const* d_in, const int* in_sizes, int n_in,
                              void* d_out, int out_size) {
    const float* x        = (const float*)d_in[0];
    const float* conv1_w  = (const float*)d_in[2];
    const float* conv1_b  = (const float*)d_in[3];
    const float* conv2_w  = (const float*)d_in[4];
    const float* conv2_b  = (const float*)d_in[5];
    const float* fc1_w    = (const float*)d_in[6];
    const float* fc1_b    = (const float*)d_in[7];
    const float* fc2_w    = (const float*)d_in[8];
    const float* fc2_b    = (const float*)d_in[9];
    const float* nbr_w    = (const float*)d_in[10];
    const float* nbr_b    = (const float*)d_in[11];
    const float* templates= (const float*)d_in[12];
    const float* proto_w  = (const float*)d_in[13];
    const float* proto_b  = (const float*)d_in[14];
    const float* glob_w1  = (const float*)d_in[15];
    const float* glob_b1  = (const float*)d_in[16];
    const float* glob_w2  = (const float*)d_in[17];
    const float* glob_b2  = (const float*)d_in[18];
    const float* cls_w    = (const float*)d_in[19];
    const float* cls_b    = (const float*)d_in[20];
    float* out = (float*)d_out;

    float *H2, *An, *P;
    __nv_bfloat16 *H0s, *H1s, *H2s, *fc1ws, *fc2ws, *nbrws, *protows;
    cudaGetSymbolAddress((void**)&H2, g_H2);
    cudaGetSymbolAddress((void**)&An, g_An);
    cudaGetSymbolAddress((void**)&P,  g_P);
    cudaGetSymbolAddress((void**)&H0s, g_H0s);
    cudaGetSymbolAddress((void**)&H1s, g_H1s);
    cudaGetSymbolAddress((void**)&H2s, g_H2s);
    cudaGetSymbolAddress((void**)&fc1ws, g_fc1ws);
    cudaGetSymbolAddress((void**)&fc2ws, g_fc2ws);
    cudaGetSymbolAddress((void**)&nbrws, g_nbrws);
    cudaGetSymbolAddress((void**)&protows, g_protows);

    const size_t conv_smem = S_TOTALF * sizeof(float);
    cudaFuncSetAttribute(conv_fused_kernel, cudaFuncAttributeMaxDynamicSharedMemorySize, (int)conv_smem);
    const int gsmem = 4 * STAGE_BYTES;   // 98304
    cudaFuncSetAttribute(mma_gemm<1, false, true>,  cudaFuncAttributeMaxDynamicSharedMemorySize, gsmem);
    cudaFuncSetAttribute(mma_gemm<1, true,  true>,  cudaFuncAttributeMaxDynamicSharedMemorySize, gsmem);
    cudaFuncSetAttribute(mma_gemm<2, true,  false>, cudaFuncAttributeMaxDynamicSharedMemorySize, gsmem);

    // no noops: capture (4th launch incl. harness pre-launch) = fc1 mma_gemm
    conv_fused_kernel<<<NN, 512, conv_smem>>>(x, conv1_w, conv1_b, conv2_w, conv2_b);

    const int cvt_total = CVT_N1 + CVT_N2 + CVT_N3 + CVT_N4;
    cvt_all_kernel<<<(cvt_total + 255) / 256, 256>>>(fc1_w, fc2_w, nbr_w, proto_w);

    mma_gemm<1, false, true><<<dim3(HDIM / 64, NN / 128), 256, gsmem>>>(
        H0s, fc1ws, fc1_b, nullptr, H1s, H0DIM, 3 * H0DIM, H0DIM, 3 * H0DIM, H0DIM, 0, 3 * HDIM, HDIM);
    mma_gemm<1, true, true><<<dim3(HDIM / 64, NN / 128), 256, gsmem>>>(
        H1s, fc2ws, fc2_b, H2, H2s, HDIM, 3 * HDIM, HDIM, 3 * HDIM, HDIM, H2DIM, 3 * H2DIM, H2DIM);
    mma_gemm<2, true, false><<<dim3(HDIM / 64, NN / 128), 256, gsmem>>>(
        H2s, nbrws, nbr_b, An, nullptr, HDIM, 3 * H2DIM, H2DIM, 3 * HDIM, HDIM, HDIM, 0, 0);
    nbr_kernel<<<NN / 8, 256>>>();
    mma_gemm<2, true, false><<<dim3(H2DIM / 64, NN / 128), 256, gsmem>>>(
        H2s, protows, proto_b, P, nullptr, H2DIM, 3 * H2DIM, H2DIM, 3 * H2DIM, H2DIM, H2DIM, 0, 0);

    tlogits_kernel<<<NN, 256>>>(templates);
    betas_kernel<<<TDIM, 256>>>();
    embs_part_kernel<<<dim3(H2DIM / 128, NSPLIT), 128>>>();
    embs_reduce_kernel<<<(TDIM * H2DIM + 255) / 256, 256>>>();
    glob1_kernel<<<dim3(16, TDIM), 256>>>(glob_w1, glob_b1);
    final2_kernel<<<1, 256>>>(glob_w2, glob_b2, cls_w, cls_b, out, out_size);
}

// round 16
// speedup vs baseline: 1.0556x; 1.0111x over previous
#include <cuda_runtime.h>
#include <cuda_bf16.h>
#include <math.h>

typedef unsigned long long ull;
typedef unsigned int u32;

// ---------------- problem constants ----------------
#define NN        2048
#define P1        14
#define H0DIM     1728
#define HDIM      512
#define H2DIM     1024
#define TDIM      10
#define NSPLIT    16

// conv SMEM layout (floats)
#define S_IMG     0
#define S_W1      1056
#define S_B1      1632
#define S_B2      1668
#define S_POOL1   1716
#define S_W2      8772
#define W2STRIDE  50
#define S_TOTALF  (8772 + 16200)

#define SWZ(off)  ((off) ^ (((off) >> 3) & 0x70))

// cvt work appended to conv grid
#define CVT_BLOCKS 192
#define CVT_N1 884736
#define CVT_N2 262144
#define CVT_N3 262144
#define CVT_N4 1048576
#define CVT_TOTAL (CVT_N1 + CVT_N2 + CVT_N3 + CVT_N4)

// ---------------- scratch ----------------
__device__ float g_H2[(size_t)NN * H2DIM];
__device__ float g_An[(size_t)NN * HDIM];
__device__ float g_P[(size_t)NN * H2DIM];
__device__ float g_L[TDIM * NN];
__device__ float g_betas[TDIM * NN];
__device__ float g_embs_part[NSPLIT * TDIM * H2DIM];
__device__ float g_embs[TDIM * H2DIM];
__device__ float g_V[TDIM * 128];

__device__ __align__(256) __nv_bfloat16 g_H0s[(size_t)NN * 3 * H0DIM];
__device__ __align__(256) __nv_bfloat16 g_H1s[(size_t)NN * 3 * HDIM];
__device__ __align__(256) __nv_bfloat16 g_H2s[(size_t)NN * 3 * H2DIM];
__device__ __align__(256) __nv_bfloat16 g_fc1ws[(size_t)HDIM * 3 * H0DIM];
__device__ __align__(256) __nv_bfloat16 g_fc2ws[(size_t)HDIM * 3 * HDIM];
__device__ __align__(256) __nv_bfloat16 g_nbrws[(size_t)HDIM * 3 * HDIM];
__device__ __align__(256) __nv_bfloat16 g_protows[(size_t)H2DIM * 3 * H2DIM];

__device__ __forceinline__ u32 smem_u32(const void* p) {
    u32 a; asm("{ .reg .u64 t; cvta.to.shared.u64 t, %1; cvt.u32.u64 %0, t; }" : "=r"(a) : "l"(p));
    return a;
}
__device__ __forceinline__ void cp16(u32 dst, const void* src) {
    asm volatile("cp.async.ca.shared.global [%0], [%1], 16;" :: "r"(dst), "l"(src));
}
__device__ __forceinline__ void cp_commit() { asm volatile("cp.async.commit_group;" ::: "memory"); }
template <int N>
__device__ __forceinline__ void cp_wait() { asm volatile("cp.async.wait_group %0;" :: "n"(N) : "memory"); }

// ---------------- fused conv + appended cvt blocks ----------------
__device__ __forceinline__ ull pack2(float lo, float hi) {
    ull r; asm("mov.b64 %0, {%1, %2};" : "=l"(r) : "f"(lo), "f"(hi)); return r;
}
__device__ __forceinline__ void unpack2(ull v, float& lo, float& hi) {
    asm("mov.b64 {%0, %1}, %2;" : "=f"(lo), "=f"(hi) : "l"(v));
}
__device__ __forceinline__ void fma2(ull& d, ull a, ull b) {
    asm("fma.rn.f32x2 %0, %1, %2, %0;" : "+l"(d) : "l"(a), "l"(b));
}

__device__ __forceinline__ void cvt_one(const float* __restrict__ w, __nv_bfloat16* __restrict__ o,
                                        int K, int li) {
    int n = li / K, k = li - n * K;
    float v = w[li];
    __nv_bfloat16 hi = __float2bfloat16(v);
    __nv_bfloat16 lo = __float2bfloat16(v - __bfloat162float(hi));
    size_t base = (size_t)n * 3 * K + k;
    o[base] = hi; o[base + K] = lo; o[base + 2 * K] = hi;
}

__global__ __launch_bounds__(512, 2)
void conv_fused_kernel(const float* __restrict__ x,
                       const float* __restrict__ w1,
                       const float* __restrict__ b1,
                       const float* __restrict__ w2,
                       const float* __restrict__ b2,
                       const float* __restrict__ fc1w,
                       const float* __restrict__ fc2w,
                       const float* __restrict__ nbrw,
                       const float* __restrict__ protow) {
    int n = blockIdx.x, tid = threadIdx.x;

    if (n >= NN) {
        // ---- cvt blocks: weight hi/lo split, grid-stride ----
        int idx = (n - NN) * 512 + tid;
        for (; idx < CVT_TOTAL; idx += CVT_BLOCKS * 512) {
            if (idx < CVT_N1) cvt_one(fc1w, g_fc1ws, H0DIM, idx);
            else if (idx < CVT_N1 + CVT_N2) cvt_one(fc2w, g_fc2ws, HDIM, idx - CVT_N1);
            else if (idx < CVT_N1 + CVT_N2 + CVT_N3) cvt_one(nbrw, g_nbrws, HDIM, idx - CVT_N1 - CVT_N2);
            else cvt_one(protow, g_protows, H2DIM, idx - CVT_N1 - CVT_N2 - CVT_N3);
        }
        return;
    }

    extern __shared__ float sm[];
    float* s_img   = sm + S_IMG;
    float* s_w1    = sm + S_W1;
    float* s_b1    = sm + S_B1;
    float* s_b2    = sm + S_B2;
    float* s_pool1 = sm + S_POOL1;
    float* s_w2    = sm + S_W2;

    const float* xin = x + (size_t)n * 1024;

    for (int i = tid; i < 1024; i += 512) {
        int r = i >> 5, c = i & 31;
        s_img[r * 33 + c] = xin[i];
    }
    for (int i = tid; i < 576; i += 512) s_w1[i] = w1[i];
    if (tid < 36) s_b1[tid] = b1[tid];
    else if (tid >= 64 && tid < 112) s_b2[tid - 64] = b2[tid - 64];
    for (int i = tid; i < 15552; i += 512) {
        int ch = i / 324, r = i - ch * 324;
        s_w2[r * W2STRIDE + ch] = w2[i];
    }
    __syncthreads();

    if (tid < 504) {
        int ch = tid / 14, py = tid % 14;
        const float4* wp = (const float4*)&s_w1[ch * 16];
        float4 a0 = wp[0], a1 = wp[1], a2 = wp[2], a3 = wp[3];
        float wr[16] = {a0.x,a0.y,a0.z,a0.w, a1.x,a1.y,a1.z,a1.w,
                        a2.x,a2.y,a2.z,a2.w, a3.x,a3.y,a3.z,a3.w};
        float bias1 = s_b1[ch];
        float* prow = s_pool1 + ch * 196 + py * 14;
        const float* ibase = s_img + (2 * py) * 33;
        for (int px = 0; px < 14; px++) {
            float s00 = 0.f, s01 = 0.f, s10 = 0.f, s11 = 0.f;
            const float* ip = ibase + 2 * px;
            #pragma unroll
            for (int yy = 0; yy < 5; yy++) {
                float r0 = ip[yy * 33 + 0], r1 = ip[yy * 33 + 1], r2 = ip[yy * 33 + 2];
                float r3 = ip[yy * 33 + 3], r4 = ip[yy * 33 + 4];
                if (yy <= 3) {
                    const float* w = wr + yy * 4;
                    s00 += r0 * w[0] + r1 * w[1] + r2 * w[2] + r3 * w[3];
                    s01 += r1 * w[0] + r2 * w[1] + r3 * w[2] + r4 * w[3];
                }
                if (yy >= 1) {
                    const float* w = wr + (yy - 1) * 4;
                    s10 += r0 * w[0] + r1 * w[1] + r2 * w[2] + r3 * w[3];
                    s11 += r1 * w[0] + r2 * w[1] + r3 * w[2] + r4 * w[3];
                }
            }
            float m = fmaxf(fmaxf(s00, s01), fmaxf(s10, s11));
            prow[px] = fmaxf(m + bias1, 0.f);
        }
    }
    __syncthreads();

    // conv2: thread = (16-ch group g, position pair q/q+72)
    ull acc0[8], acc1[8];
    int g = tid / 72, q = tid - g * 72;
    if (tid < 216) {
        int cy = q / 12, cx = q - cy * 12;
        #pragma unroll
        for (int j = 0; j < 8; j++) { acc0[j] = 0ull; acc1[j] = 0ull; }
        const float* in0 = s_pool1 + cy * 14 + cx;
        const float* in1 = in0 + 84;
        const float* wgb = s_w2 + g * 16;
        for (int c = 0; c < 36; c++) {
            #pragma unroll
            for (int k = 0; k < 9; k++) {
                int ioff = c * 196 + (k / 3) * 14 + (k % 3);
                float v0 = in0[ioff], v1 = in1[ioff];
                ull vv0 = pack2(v0, v0), vv1 = pack2(v1, v1);
                const ull* qw = (const ull*)(wgb + (c * 9 + k) * W2STRIDE);
                #pragma unroll
                for (int j = 0; j < 8; j++) {
                    ull w = qw[j];
                    fma2(acc0[j], w, vv0);
                    fma2(acc1[j], w, vv1);
                }
            }
        }
    }
    __syncthreads();
    if (tid < 216) {
        float* o0 = s_w2 + q * 49 + g * 16;
        float* o1 = s_w2 + (q + 72) * 49 + g * 16;
        #pragma unroll
        for (int j = 0; j < 8; j++) {
            float lo, hi;
            unpack2(acc0[j], lo, hi); o0[2 * j] = lo; o0[2 * j + 1] = hi;
            unpack2(acc1[j], lo, hi); o1[2 * j] = lo; o1[2 * j + 1] = hi;
        }
    }
    __syncthreads();

    __nv_bfloat16* outb = g_H0s + (size_t)n * 3 * H0DIM;
    for (int o = tid; o < 1728; o += 512) {
        int ch = o / 36, pp = o - ch * 36;
        int py = pp / 6, px = pp - py * 6;
        int i00 = (2 * py) * 12 + 2 * px;
        float m = fmaxf(fmaxf(s_w2[i00 * 49 + ch],        s_w2[(i00 + 1)  * 49 + ch]),
                        fmaxf(s_w2[(i00 + 12) * 49 + ch], s_w2[(i00 + 13) * 49 + ch]));
        float v = fmaxf(m + s_b2[ch], 0.f);
        __nv_bfloat16 hi = __float2bfloat16(v);
        __nv_bfloat16 lo = __float2bfloat16(v - __bfloat162float(hi));
        outb[o] = hi; outb[1728 + o] = hi; outb[3456 + o] = lo;
    }
}

// ---------------- mma.sync bf16 GEMM 128x64, 8 warps, 4-stage, B via x4 -------
#define STAGE_BYTES 24576
template <int ACT, bool WF, bool WS>
__global__ __launch_bounds__(256)
void mma_gemm(const __nv_bfloat16* __restrict__ A, const __nv_bfloat16* __restrict__ B,
              const float* __restrict__ bias, float* __restrict__ Cf, __nv_bfloat16* __restrict__ Cs,
              int K, int rsA, int ssA, int rsB, int ssB, int ldc, int ldcs, int slotC) {
    extern __shared__ char smem[];
    u32 sb = smem_u32(smem);
    const int tid = threadIdx.x, wid = tid >> 5, lane = tid & 31;
    const int bm = blockIdx.y * 128, bn = blockIdx.x * 64;
    const int wm = wid & 1, wn = wid >> 1;
    const int lr = tid >> 3, lg = tid & 7;

    auto cp_tile = [&](int kc, int buf) {   // kc in elements (multiple of 64)
        int slot = kc / K, off = kc - slot * K;
        u32 base = sb + buf * STAGE_BYTES;
        const __nv_bfloat16* Ab = A + (size_t)bm * rsA + (size_t)slot * ssA + off;
        #pragma unroll
        for (int i = 0; i < 4; i++)
            cp16(base + SWZ((lr + i * 32) * 128 + lg * 16), Ab + (size_t)(lr + i * 32) * rsA + lg * 8);
        const __nv_bfloat16* Bb = B + (size_t)bn * rsB + (size_t)slot * ssB + off;
        #pragma unroll
        for (int i = 0; i < 2; i++)
            cp16(base + 16384 + SWZ((lr + i * 32) * 128 + lg * 16), Bb + (size_t)(lr + i * 32) * rsB + lg * 8);
    };

    float acc[4][2][4];
    #pragma unroll
    for (int mi = 0; mi < 4; mi++)
        #pragma unroll
        for (int ni = 0; ni < 2; ni++)
            #pragma unroll
            for (int j = 0; j < 4; j++) acc[mi][ni][j] = 0.f;

    const int nch = (3 * K) / 64;
    cp_tile(0, 0); cp_commit();
    cp_tile(64, 1); cp_commit();
    cp_tile(128, 2); cp_commit();

    for (int c = 0; c < nch; c++) {
        if (c + 2 < nch) cp_wait<2>();
        else if (c + 1 < nch) cp_wait<1>();
        else cp_wait<0>();
        __syncthreads();
        if (c + 3 < nch) { cp_tile((c + 3) * 64, (c + 3) & 3); cp_commit(); }

        u32 sA = sb + (c & 3) * STAGE_BYTES, sBB = sA + 16384;
        #pragma unroll
        for (int ks = 0; ks < 4; ks++) {
            u32 a[4][4], b[4];
            #pragma unroll
            for (int mi = 0; mi < 4; mi++) {
                int row = wm * 64 + mi * 16 + (lane & 15);
                int gq = ks * 2 + (lane >> 4);
                u32 ad = sA + SWZ(row * 128 + gq * 16);
                asm volatile("ldmatrix.sync.aligned.m8n8.x4.shared.b16 {%0,%1,%2,%3}, [%4];"
                             : "=r"(a[mi][0]), "=r"(a[mi][1]), "=r"(a[mi][2]), "=r"(a[mi][3]) : "r"(ad));
            }
            {
                int row = wn * 16 + ((lane >> 4) & 1) * 8 + (lane & 7);
                int gq = ks * 2 + ((lane >> 3) & 1);
                u32 ad = sBB + SWZ(row * 128 + gq * 16);
                asm volatile("ldmatrix.sync.aligned.m8n8.x4.shared.b16 {%0,%1,%2,%3}, [%4];"
                             : "=r"(b[0]), "=r"(b[1]), "=r"(b[2]), "=r"(b[3]) : "r"(ad));
            }
            #pragma unroll
            for (int mi = 0; mi < 4; mi++) {
                asm volatile("mma.sync.aligned.m16n8k16.row.col.f32.bf16.bf16.f32 "
                             "{%0,%1,%2,%3}, {%4,%5,%6,%7}, {%8,%9}, {%0,%1,%2,%3};"
                             : "+f"(acc[mi][0][0]), "+f"(acc[mi][0][1]), "+f"(acc[mi][0][2]), "+f"(acc[mi][0][3])
                             : "r"(a[mi][0]), "r"(a[mi][1]), "r"(a[mi][2]), "r"(a[mi][3]),
                               "r"(b[0]), "r"(b[1]));
                asm volatile("mma.sync.aligned.m16n8k16.row.col.f32.bf16.bf16.f32 "
                             "{%0,%1,%2,%3}, {%4,%5,%6,%7}, {%8,%9}, {%0,%1,%2,%3};"
                             : "+f"(acc[mi][1][0]), "+f"(acc[mi][1][1]), "+f"(acc[mi][1][2]), "+f"(acc[mi][1][3])
                             : "r"(a[mi][0]), "r"(a[mi][1]), "r"(a[mi][2]), "r"(a[mi][3]),
                               "r"(b[2]), "r"(b[3]));
            }
        }
        __syncthreads();
    }

    #pragma unroll
    for (int ni = 0; ni < 2; ni++) {
        int c0 = bn + wn * 16 + ni * 8 + (lane & 3) * 2;
        float b0 = bias[c0], b1 = bias[c0 + 1];
        #pragma unroll
        for (int mi = 0; mi < 4; mi++) {
            int r0 = bm + wm * 64 + mi * 16 + (lane >> 2);
            float v0 = acc[mi][ni][0] + b0, v1 = acc[mi][ni][1] + b1;
            float v2 = acc[mi][ni][2] + b0, v3 = acc[mi][ni][3] + b1;
            if (ACT == 1) { v0 = fmaxf(v0, 0.f); v1 = fmaxf(v1, 0.f); v2 = fmaxf(v2, 0.f); v3 = fmaxf(v3, 0.f); }
            if (ACT == 2) { v0 = tanhf(v0); v1 = tanhf(v1); v2 = tanhf(v2); v3 = tanhf(v3); }
            if (WF) {
                *(float2*)(Cf + (size_t)r0 * ldc + c0)       = make_float2(v0, v1);
                *(float2*)(Cf + (size_t)(r0 + 8) * ldc + c0) = make_float2(v2, v3);
            }
            if (WS) {
                __nv_bfloat16* s0 = Cs + (size_t)r0 * ldcs + c0;
                __nv_bfloat16* s1 = Cs + (size_t)(r0 + 8) * ldcs + c0;
                float vv[2][2] = {{v0, v1}, {v2, v3}};
                __nv_bfloat16* sp[2] = {s0, s1};
                #pragma unroll
                for (int rr = 0; rr < 2; rr++)
                    #pragma unroll
                    for (int jj = 0; jj < 2; jj++) {
                        float v = vv[rr][jj];
                        __nv_bfloat16 hi = __float2bfloat16(v);
                        __nv_bfloat16 lo = __float2bfloat16(v - __bfloat162float(hi));
                        sp[rr][jj] = hi; sp[rr][slotC + jj] = hi; sp[rr][2 * slotC + jj] = lo;
                    }
            }
        }
    }
}

// ---------------- neighborhood attention ----------------
__global__ void nbr_kernel() {
    int gwarp = (blockIdx.x * blockDim.x + threadIdx.x) >> 5;
    int lane = threadIdx.x & 31;
    if (gwarp >= NN) return;
    int i = gwarp;
    int r = i >> 6, c = i & 63;

    float hi[16];
    const float* Hi = g_H2 + (size_t)i * H2DIM;
    #pragma unroll
    for (int u = 0; u < 16; u++) hi[u] = Hi[lane + 32 * u];

    int nbrs[8]; int cnt = 0;
    for (int dr = -1; dr <= 1; dr++)
        for (int dc = -1; dc <= 1; dc++) {
            if (dr == 0 && dc == 0) continue;
            int rr = r + dr, cc = c + dc;
            if (rr >= 0 && rr < 32 && cc >= 0 && cc < 64) nbrs[cnt++] = rr * 64 + cc;
        }

    float dots[8];
    for (int q = 0; q < cnt; q++) {
        const float* An = g_An + (size_t)nbrs[q] * HDIM;
        float s = 0.f;
        #pragma unroll
        for (int u = 0; u < 16; u++) s += hi[u] * An[lane + 32 * u];
        #pragma unroll
        for (int o = 16; o; o >>= 1) s += __shfl_xor_sync(0xffffffffu, s, o);
        dots[q] = s;
    }
    float m = -3.0e38f;
    for (int q = 0; q < cnt; q++) m = fmaxf(m, dots[q]);
    float ssum = 0.f;
    for (int q = 0; q < cnt; q++) { dots[q] = expf(dots[q] - m); ssum += dots[q]; }
    float inv = 1.f / ssum;

    float accv[16];
    #pragma unroll
    for (int u = 0; u < 16; u++) accv[u] = 0.f;
    for (int q = 0; q < cnt; q++) {
        float a = dots[q] * inv;
        const float* Hj = g_H2 + (size_t)nbrs[q] * H2DIM;
        #pragma unroll
        for (int u = 0; u < 16; u++) accv[u] += a * Hj[lane + 32 * u];
    }
    float* o = g_H2 + (size_t)i * H2DIM + HDIM;
    __nv_bfloat16* os = g_H2s + (size_t)i * 3 * H2DIM;
    #pragma unroll
    for (int u = 0; u < 16; u++) {
        float v = accv[u];
        int col = 512 + lane + 32 * u;
        o[lane + 32 * u] = v;
        __nv_bfloat16 vh = __float2bfloat16(v);
        __nv_bfloat16 vl = __float2bfloat16(v - __bfloat162float(vh));
        os[col] = vh; os[1024 + col] = vh; os[2048 + col] = vl;
    }
}

// ---------------- template logits (SMEM row cache) ----------------
__global__ void tlogits_kernel(const float* __restrict__ templates) {
    __shared__ float prow[H2DIM];
    int n = blockIdx.x, tid = threadIdx.x;  // 256
    const float* p = g_P + (size_t)n * H2DIM;
    for (int i = tid; i < H2DIM; i += 256) prow[i] = p[i];
    __syncthreads();
    int w = tid >> 5, lane = tid & 31;
    for (int t = w; t < TDIM; t += 8) {
        const float* tm = templates + (size_t)t * H2DIM;
        float s = 0.f;
        #pragma unroll 8
        for (int k = lane; k < H2DIM; k += 32) s += prow[k] * tm[k];
        #pragma unroll
        for (int o = 16; o; o >>= 1) s += __shfl_xor_sync(0xffffffffu, s, o);
        if (lane == 0) g_L[t * NN + n] = s;
    }
}

// ---------------- betas softmax ----------------
__global__ void betas_kernel() {
    int t = blockIdx.x, tid = threadIdx.x;
    __shared__ float red[256];
    __shared__ float smax, ssum;
    const float* L = g_L + t * NN;
    float m = -3.0e38f;
    for (int n = tid; n < NN; n += 256) m = fmaxf(m, L[n]);
    red[tid] = m; __syncthreads();
    for (int s = 128; s; s >>= 1) { if (tid < s) red[tid] = fmaxf(red[tid], red[tid + s]); __syncthreads(); }
    if (tid == 0) smax = red[0];
    __syncthreads();
    float acc = 0.f;
    for (int n = tid; n < NN; n += 256) acc += expf(L[n] - smax);
    red[tid] = acc; __syncthreads();
    for (int s = 128; s; s >>= 1) { if (tid < s) red[tid] += red[tid + s]; __syncthreads(); }
    if (tid == 0) ssum = 1.f / red[0];
    __syncthreads();
    for (int n = tid; n < NN; n += 256)
        g_betas[t * NN + n] = expf(L[n] - smax) * ssum;
}

// ---------------- embs partials ----------------
__global__ void embs_part_kernel() {
    __shared__ float bsh[TDIM * 128];
    int col = blockIdx.x * 128 + threadIdx.x;
    int s = blockIdx.y;
    int n0 = s * 128;
    for (int i = threadIdx.x; i < TDIM * 128; i += 128) {
        int t = i >> 7, nl = i & 127;
        bsh[i] = g_betas[t * NN + n0 + nl];
    }
    __syncthreads();
    float acc[TDIM];
    #pragma unroll
    for (int t = 0; t < TDIM; t++) acc[t] = 0.f;
    for (int nl = 0; nl < 128; nl++) {
        float h = g_H2[(size_t)(n0 + nl) * H2DIM + col];
        #pragma unroll
        for (int t = 0; t < TDIM; t++) acc[t] += bsh[t * 128 + nl] * h;
    }
    #pragma unroll
    for (int t = 0; t < TDIM; t++)
        g_embs_part[(size_t)(s * TDIM + t) * H2DIM + col] = acc[t];
}

// ---------------- glob1 (with fused embs reduce) ----------------
__global__ void glob1_kernel(const float* __restrict__ glob_w1, const float* __restrict__ glob_b1) {
    __shared__ float esh[H2DIM];
    int t = blockIdx.y, tid = threadIdx.x;  // 256
    // reduce embs[t] into SMEM; block x==0 publishes for final2
    for (int k = tid; k < H2DIM; k += 256) {
        float s = 0.f;
        #pragma unroll
        for (int p = 0; p < NSPLIT; p++) s += g_embs_part[(size_t)p * TDIM * H2DIM + t * H2DIM + k];
        esh[k] = s;
        if (blockIdx.x == 0) g_embs[t * H2DIM + k] = s;
    }
    __syncthreads();
    int w = tid >> 5, lane = tid & 31;
    int j = blockIdx.x * 8 + w;
    const float* wr = glob_w1 + (size_t)j * H2DIM;
    float s = 0.f;
    #pragma unroll 8
    for (int k = lane; k < H2DIM; k += 32) s += wr[k] * esh[k];
    #pragma unroll
    for (int o = 16; o; o >>= 1) s += __shfl_xor_sync(0xffffffffu, s, o);
    if (lane == 0) g_V[t * 128 + j] = tanhf(s + glob_b1[j]);
}

// ---------------- final2 ----------------
__global__ void final2_kernel(const float* __restrict__ glob_w2, const float* __restrict__ glob_b2,
                              const float* __restrict__ cls_w,  const float* __restrict__ cls_b,
                              float* __restrict__ out, int out_size) {
    __shared__ float vsh[TDIM * 128];
    __shared__ float Msh[H2DIM];
    __shared__ float gam[TDIM];
    __shared__ float psh[2];
    int tid = threadIdx.x;

    for (int i = tid; i < TDIM * 128; i += 256) vsh[i] = g_V[i];
    __syncthreads();

    if (tid < TDIM) {
        float s = glob_b2[0];
        for (int j = 0; j < 128; j++) s += glob_w2[j] * vsh[tid * 128 + j];
        gam[tid] = s;
    }
    __syncthreads();
    if (tid == 0) {
        float m = gam[0];
        for (int t = 1; t < TDIM; t++) m = fmaxf(m, gam[t]);
        float ss = 0.f;
        for (int t = 0; t < TDIM; t++) { gam[t] = expf(gam[t] - m); ss += gam[t]; }
        float inv = 1.f / ss;
        for (int t = 0; t < TDIM; t++) gam[t] *= inv;
    }
    __syncthreads();

    for (int k = tid; k < H2DIM; k += 256) {
        float s = 0.f;
        #pragma unroll
        for (int t = 0; t < TDIM; t++) s += gam[t] * g_embs[t * H2DIM + k];
        Msh[k] = s;
    }
    __syncthreads();

    if (tid < 64) {
        int c = tid >> 5, lane = tid & 31;
        float s = 0.f;
        for (int k = lane; k < H2DIM; k += 32) s += cls_w[(size_t)c * H2DIM + k] * Msh[k];
        #pragma unroll
        for (int o = 16; o; o >>= 1) s += __shfl_xor_sync(0xffffffffu, s, o);
        if (lane == 0) {
            float p = 1.f / (1.f + expf(-(s + cls_b[c])));
            psh[c] = p;
            if (c < out_size) out[c] = p;
        }
    }
    __syncthreads();
    if (tid == 0 && out_size > 2) out[2] = (psh[1] > psh[0]) ? 1.0f : 0.0f;

    for (int n = tid; n < NN; n += 256) {
        float s = 0.f;
        #pragma unroll
        for (int t = 0; t < TDIM; t++) s += gam[t] * g_betas[t * NN + n];
        if (3 + n < out_size) out[3 + n] = s;
    }
}

// ---------------- launch ----------------
extern "C" void kernel_launch(void* const* d_in, const int* in_sizes, int n_in,
                              void* d_out, int out_size) {
    const float* x        = (const float*)d_in[0];
    const float* conv1_w  = (const float*)d_in[2];
    const float* conv1_b  = (const float*)d_in[3];
    const float* conv2_w  = (const float*)d_in[4];
    const float* conv2_b  = (const float*)d_in[5];
    const float* fc1_w    = (const float*)d_in[6];
    const float* fc1_b    = (const float*)d_in[7];
    const float* fc2_w    = (const float*)d_in[8];
    const float* fc2_b    = (const float*)d_in[9];
    const float* nbr_w    = (const float*)d_in[10];
    const float* nbr_b    = (const float*)d_in[11];
    const float* templates= (const float*)d_in[12];
    const float* proto_w  = (const float*)d_in[13];
    const float* proto_b  = (const float*)d_in[14];
    const float* glob_w1  = (const float*)d_in[15];
    const float* glob_b1  = (const float*)d_in[16];
    const float* glob_w2  = (const float*)d_in[17];
    const float* glob_b2  = (const float*)d_in[18];
    const float* cls_w    = (const float*)d_in[19];
    const float* cls_b    = (const float*)d_in[20];
    float* out = (float*)d_out;

    float *H2, *An, *P;
    __nv_bfloat16 *H0s, *H1s, *H2s, *fc1ws, *fc2ws, *nbrws, *protows;
    cudaGetSymbolAddress((void**)&H2, g_H2);
    cudaGetSymbolAddress((void**)&An, g_An);
    cudaGetSymbolAddress((void**)&P,  g_P);
    cudaGetSymbolAddress((void**)&H0s, g_H0s);
    cudaGetSymbolAddress((void**)&H1s, g_H1s);
    cudaGetSymbolAddress((void**)&H2s, g_H2s);
    cudaGetSymbolAddress((void**)&fc1ws, g_fc1ws);
    cudaGetSymbolAddress((void**)&fc2ws, g_fc2ws);
    cudaGetSymbolAddress((void**)&nbrws, g_nbrws);
    cudaGetSymbolAddress((void**)&protows, g_protows);

    const size_t conv_smem = S_TOTALF * sizeof(float);
    cudaFuncSetAttribute(conv_fused_kernel, cudaFuncAttributeMaxDynamicSharedMemorySize, (int)conv_smem);
    const int gsmem = 4 * STAGE_BYTES;   // 98304
    cudaFuncSetAttribute(mma_gemm<1, false, true>,  cudaFuncAttributeMaxDynamicSharedMemorySize, gsmem);
    cudaFuncSetAttribute(mma_gemm<1, true,  true>,  cudaFuncAttributeMaxDynamicSharedMemorySize, gsmem);
    cudaFuncSetAttribute(mma_gemm<2, true,  false>, cudaFuncAttributeMaxDynamicSharedMemorySize, gsmem);

    // conv + appended cvt blocks (cvt overlaps conv's drain wave)
    conv_fused_kernel<<<NN + CVT_BLOCKS, 512, conv_smem>>>(
        x, conv1_w, conv1_b, conv2_w, conv2_b, fc1_w, fc2_w, nbr_w, proto_w);

    mma_gemm<1, false, true><<<dim3(HDIM / 64, NN / 128), 256, gsmem>>>(
        H0s, fc1ws, fc1_b, nullptr, H1s, H0DIM, 3 * H0DIM, H0DIM, 3 * H0DIM, H0DIM, 0, 3 * HDIM, HDIM);
    mma_gemm<1, true, true><<<dim3(HDIM / 64, NN / 128), 256, gsmem>>>(
        H1s, fc2ws, fc2_b, H2, H2s, HDIM, 3 * HDIM, HDIM, 3 * HDIM, HDIM, H2DIM, 3 * H2DIM, H2DIM);
    mma_gemm<2, true, false><<<dim3(HDIM / 64, NN / 128), 256, gsmem>>>(
        H2s, nbrws, nbr_b, An, nullptr, HDIM, 3 * H2DIM, H2DIM, 3 * HDIM, HDIM, HDIM, 0, 0);
    nbr_kernel<<<NN / 8, 256>>>();
    mma_gemm<2, true, false><<<dim3(H2DIM / 64, NN / 128), 256, gsmem>>>(
        H2s, protows, proto_b, P, nullptr, H2DIM, 3 * H2DIM, H2DIM, 3 * H2DIM, H2DIM, H2DIM, 0, 0);

    tlogits_kernel<<<NN, 256>>>(templates);
    betas_kernel<<<TDIM, 256>>>();
    embs_part_kernel<<<dim3(H2DIM / 128, NSPLIT), 128>>>();
    glob1_kernel<<<dim3(16, TDIM), 256>>>(glob_w1, glob_b1);
    final2_kernel<<<1, 256>>>(glob_w2, glob_b2, cls_w, cls_b, out, out_size);
}

// round 17
// speedup vs baseline: 1.1004x; 1.0424x over previous
#include <cuda_runtime.h>
#include <cuda_bf16.h>
#include <math.h>

typedef unsigned long long ull;
typedef unsigned int u32;

// ---------------- problem constants ----------------
#define NN        2048
#define P1        14
#define H0DIM     1728
#define HDIM      512
#define H2DIM     1024
#define TDIM      10
#define NSPLIT    16

// conv SMEM layout (floats)
#define S_IMG     0
#define S_W1      1056
#define S_B1      1632
#define S_B2      1668
#define S_POOL1   1716
#define S_W2      8772
#define W2STRIDE  50
#define S_TOTALF  (8772 + 16200)

#define SWZ(off)  ((off) ^ (((off) >> 3) & 0x70))

// cvt work appended to conv grid
#define CVT_BLOCKS 192
#define CVT_N1 884736
#define CVT_N2 262144
#define CVT_N3 262144
#define CVT_N4 1048576
#define CVT_TOTAL (CVT_N1 + CVT_N2 + CVT_N3 + CVT_N4)

// ---------------- scratch ----------------
__device__ float g_H2[(size_t)NN * H2DIM];
__device__ float g_An[(size_t)NN * HDIM];
__device__ float g_P[(size_t)NN * H2DIM];
__device__ float g_L[TDIM * NN];
__device__ float g_betas[TDIM * NN];
__device__ float g_embs_part[NSPLIT * TDIM * H2DIM];
__device__ float g_embs[TDIM * H2DIM];
__device__ float g_V[TDIM * 128];

__device__ __align__(256) __nv_bfloat16 g_H0s[(size_t)NN * 3 * H0DIM];
__device__ __align__(256) __nv_bfloat16 g_H1s[(size_t)NN * 3 * HDIM];
__device__ __align__(256) __nv_bfloat16 g_H2s[(size_t)NN * 3 * H2DIM];
__device__ __align__(256) __nv_bfloat16 g_fc1ws[(size_t)HDIM * 3 * H0DIM];
__device__ __align__(256) __nv_bfloat16 g_fc2ws[(size_t)HDIM * 3 * HDIM];
__device__ __align__(256) __nv_bfloat16 g_nbrws[(size_t)HDIM * 3 * HDIM];
__device__ __align__(256) __nv_bfloat16 g_protows[(size_t)H2DIM * 3 * H2DIM];

__device__ __forceinline__ u32 smem_u32(const void* p) {
    u32 a; asm("{ .reg .u64 t; cvta.to.shared.u64 t, %1; cvt.u32.u64 %0, t; }" : "=r"(a) : "l"(p));
    return a;
}
__device__ __forceinline__ void cp16(u32 dst, const void* src) {
    asm volatile("cp.async.ca.shared.global [%0], [%1], 16;" :: "r"(dst), "l"(src));
}
__device__ __forceinline__ void cp_commit() { asm volatile("cp.async.commit_group;" ::: "memory"); }
template <int N>
__device__ __forceinline__ void cp_wait() { asm volatile("cp.async.wait_group %0;" :: "n"(N) : "memory"); }

// ---------------- fused conv + appended cvt blocks ----------------
__device__ __forceinline__ ull pack2(float lo, float hi) {
    ull r; asm("mov.b64 %0, {%1, %2};" : "=l"(r) : "f"(lo), "f"(hi)); return r;
}
__device__ __forceinline__ void unpack2(ull v, float& lo, float& hi) {
    asm("mov.b64 {%0, %1}, %2;" : "=f"(lo), "=f"(hi) : "l"(v));
}
__device__ __forceinline__ void fma2(ull& d, ull a, ull b) {
    asm("fma.rn.f32x2 %0, %1, %2, %0;" : "+l"(d) : "l"(a), "l"(b));
}

__device__ __forceinline__ void cvt_one(const float* __restrict__ w, __nv_bfloat16* __restrict__ o,
                                        int K, int li) {
    int n = li / K, k = li - n * K;
    float v = w[li];
    __nv_bfloat16 hi = __float2bfloat16(v);
    __nv_bfloat16 lo = __float2bfloat16(v - __bfloat162float(hi));
    size_t base = (size_t)n * 3 * K + k;
    o[base] = hi; o[base + K] = lo; o[base + 2 * K] = hi;
}

__global__ __launch_bounds__(512, 2)
void conv_fused_kernel(const float* __restrict__ x,
                       const float* __restrict__ w1,
                       const float* __restrict__ b1,
                       const float* __restrict__ w2,
                       const float* __restrict__ b2,
                       const float* __restrict__ fc1w,
                       const float* __restrict__ fc2w,
                       const float* __restrict__ nbrw,
                       const float* __restrict__ protow) {
    int n = blockIdx.x, tid = threadIdx.x;

    if (n >= NN) {
        int idx = (n - NN) * 512 + tid;
        for (; idx < CVT_TOTAL; idx += CVT_BLOCKS * 512) {
            if (idx < CVT_N1) cvt_one(fc1w, g_fc1ws, H0DIM, idx);
            else if (idx < CVT_N1 + CVT_N2) cvt_one(fc2w, g_fc2ws, HDIM, idx - CVT_N1);
            else if (idx < CVT_N1 + CVT_N2 + CVT_N3) cvt_one(nbrw, g_nbrws, HDIM, idx - CVT_N1 - CVT_N2);
            else cvt_one(protow, g_protows, H2DIM, idx - CVT_N1 - CVT_N2 - CVT_N3);
        }
        return;
    }

    extern __shared__ float sm[];
    float* s_img   = sm + S_IMG;
    float* s_w1    = sm + S_W1;
    float* s_b1    = sm + S_B1;
    float* s_b2    = sm + S_B2;
    float* s_pool1 = sm + S_POOL1;
    float* s_w2    = sm + S_W2;

    const float* xin = x + (size_t)n * 1024;

    for (int i = tid; i < 1024; i += 512) {
        int r = i >> 5, c = i & 31;
        s_img[r * 33 + c] = xin[i];
    }
    for (int i = tid; i < 576; i += 512) s_w1[i] = w1[i];
    if (tid < 36) s_b1[tid] = b1[tid];
    else if (tid >= 64 && tid < 112) s_b2[tid - 64] = b2[tid - 64];
    for (int i = tid; i < 15552; i += 512) {
        int ch = i / 324, r = i - ch * 324;
        s_w2[r * W2STRIDE + ch] = w2[i];
    }
    __syncthreads();

    if (tid < 504) {
        int ch = tid / 14, py = tid % 14;
        const float4* wp = (const float4*)&s_w1[ch * 16];
        float4 a0 = wp[0], a1 = wp[1], a2 = wp[2], a3 = wp[3];
        float wr[16] = {a0.x,a0.y,a0.z,a0.w, a1.x,a1.y,a1.z,a1.w,
                        a2.x,a2.y,a2.z,a2.w, a3.x,a3.y,a3.z,a3.w};
        float bias1 = s_b1[ch];
        float* prow = s_pool1 + ch * 196 + py * 14;
        const float* ibase = s_img + (2 * py) * 33;
        for (int px = 0; px < 14; px++) {
            float s00 = 0.f, s01 = 0.f, s10 = 0.f, s11 = 0.f;
            const float* ip = ibase + 2 * px;
            #pragma unroll
            for (int yy = 0; yy < 5; yy++) {
                float r0 = ip[yy * 33 + 0], r1 = ip[yy * 33 + 1], r2 = ip[yy * 33 + 2];
                float r3 = ip[yy * 33 + 3], r4 = ip[yy * 33 + 4];
                if (yy <= 3) {
                    const float* w = wr + yy * 4;
                    s00 += r0 * w[0] + r1 * w[1] + r2 * w[2] + r3 * w[3];
                    s01 += r1 * w[0] + r2 * w[1] + r3 * w[2] + r4 * w[3];
                }
                if (yy >= 1) {
                    const float* w = wr + (yy - 1) * 4;
                    s10 += r0 * w[0] + r1 * w[1] + r2 * w[2] + r3 * w[3];
                    s11 += r1 * w[0] + r2 * w[1] + r3 * w[2] + r4 * w[3];
                }
            }
            float m = fmaxf(fmaxf(s00, s01), fmaxf(s10, s11));
            prow[px] = fmaxf(m + bias1, 0.f);
        }
    }
    __syncthreads();

    // conv2: thread = (16-ch group g, position pair q/q+72)
    ull acc0[8], acc1[8];
    int g = tid / 72, q = tid - g * 72;
    if (tid < 216) {
        int cy = q / 12, cx = q - cy * 12;
        #pragma unroll
        for (int j = 0; j < 8; j++) { acc0[j] = 0ull; acc1[j] = 0ull; }
        const float* in0 = s_pool1 + cy * 14 + cx;
        const float* in1 = in0 + 84;
        const float* wgb = s_w2 + g * 16;
        for (int c = 0; c < 36; c++) {
            #pragma unroll
            for (int k = 0; k < 9; k++) {
                int ioff = c * 196 + (k / 3) * 14 + (k % 3);
                float v0 = in0[ioff], v1 = in1[ioff];
                ull vv0 = pack2(v0, v0), vv1 = pack2(v1, v1);
                const ull* qw = (const ull*)(wgb + (c * 9 + k) * W2STRIDE);
                #pragma unroll
                for (int j = 0; j < 8; j++) {
                    ull w = qw[j];
                    fma2(acc0[j], w, vv0);
                    fma2(acc1[j], w, vv1);
                }
            }
        }
    }
    __syncthreads();
    if (tid < 216) {
        float* o0 = s_w2 + q * 49 + g * 16;
        float* o1 = s_w2 + (q + 72) * 49 + g * 16;
        #pragma unroll
        for (int j = 0; j < 8; j++) {
            float lo, hi;
            unpack2(acc0[j], lo, hi); o0[2 * j] = lo; o0[2 * j + 1] = hi;
            unpack2(acc1[j], lo, hi); o1[2 * j] = lo; o1[2 * j + 1] = hi;
        }
    }
    __syncthreads();

    __nv_bfloat16* outb = g_H0s + (size_t)n * 3 * H0DIM;
    for (int o = tid; o < 1728; o += 512) {
        int ch = o / 36, pp = o - ch * 36;
        int py = pp / 6, px = pp - py * 6;
        int i00 = (2 * py) * 12 + 2 * px;
        float m = fmaxf(fmaxf(s_w2[i00 * 49 + ch],        s_w2[(i00 + 1)  * 49 + ch]),
                        fmaxf(s_w2[(i00 + 12) * 49 + ch], s_w2[(i00 + 13) * 49 + ch]));
        float v = fmaxf(m + s_b2[ch], 0.f);
        __nv_bfloat16 hi = __float2bfloat16(v);
        __nv_bfloat16 lo = __float2bfloat16(v - __bfloat162float(hi));
        outb[o] = hi; outb[1728 + o] = hi; outb[3456 + o] = lo;
    }
}

// ---------------- mma.sync bf16 GEMM 128x64, warp tile 32x32 (ratio 0.5) ------
#define STAGE_BYTES 24576
template <int ACT, bool WF, bool WS>
__global__ __launch_bounds__(256)
void mma_gemm(const __nv_bfloat16* __restrict__ A, const __nv_bfloat16* __restrict__ B,
              const float* __restrict__ bias, float* __restrict__ Cf, __nv_bfloat16* __restrict__ Cs,
              int K, int rsA, int ssA, int rsB, int ssB, int ldc, int ldcs, int slotC) {
    extern __shared__ char smem[];
    u32 sb = smem_u32(smem);
    const int tid = threadIdx.x, wid = tid >> 5, lane = tid & 31;
    const int bm = blockIdx.y * 128, bn = blockIdx.x * 64;
    const int wm = wid & 3, wn = wid >> 2;   // 4 x 2 warp grid, tile 32(M) x 32(N)
    const int lr = tid >> 3, lg = tid & 7;

    auto cp_tile = [&](int kc, int buf) {   // kc in elements (multiple of 64)
        int slot = kc / K, off = kc - slot * K;
        u32 base = sb + buf * STAGE_BYTES;
        const __nv_bfloat16* Ab = A + (size_t)bm * rsA + (size_t)slot * ssA + off;
        #pragma unroll
        for (int i = 0; i < 4; i++)
            cp16(base + SWZ((lr + i * 32) * 128 + lg * 16), Ab + (size_t)(lr + i * 32) * rsA + lg * 8);
        const __nv_bfloat16* Bb = B + (size_t)bn * rsB + (size_t)slot * ssB + off;
        #pragma unroll
        for (int i = 0; i < 2; i++)
            cp16(base + 16384 + SWZ((lr + i * 32) * 128 + lg * 16), Bb + (size_t)(lr + i * 32) * rsB + lg * 8);
    };

    float acc[2][4][4];
    #pragma unroll
    for (int mi = 0; mi < 2; mi++)
        #pragma unroll
        for (int ni = 0; ni < 4; ni++)
            #pragma unroll
            for (int j = 0; j < 4; j++) acc[mi][ni][j] = 0.f;

    const int nch = (3 * K) / 64;
    cp_tile(0, 0); cp_commit();
    cp_tile(64, 1); cp_commit();
    cp_tile(128, 2); cp_commit();

    for (int c = 0; c < nch; c++) {
        if (c + 2 < nch) cp_wait<2>();
        else if (c + 1 < nch) cp_wait<1>();
        else cp_wait<0>();
        __syncthreads();
        if (c + 3 < nch) { cp_tile((c + 3) * 64, (c + 3) & 3); cp_commit(); }

        u32 sA = sb + (c & 3) * STAGE_BYTES, sBB = sA + 16384;
        #pragma unroll
        for (int ks = 0; ks < 4; ks++) {
            u32 a[2][4], b[2][4];
            #pragma unroll
            for (int mi = 0; mi < 2; mi++) {
                int row = wm * 32 + mi * 16 + (lane & 15);
                int gq = ks * 2 + (lane >> 4);
                u32 ad = sA + SWZ(row * 128 + gq * 16);
                asm volatile("ldmatrix.sync.aligned.m8n8.x4.shared.b16 {%0,%1,%2,%3}, [%4];"
                             : "=r"(a[mi][0]), "=r"(a[mi][1]), "=r"(a[mi][2]), "=r"(a[mi][3]) : "r"(ad));
            }
            #pragma unroll
            for (int nh = 0; nh < 2; nh++) {
                // x4 dual-fragment B load: 16 cols (two n8 frags), both k halves
                int row = wn * 32 + nh * 16 + ((lane >> 4) & 1) * 8 + (lane & 7);
                int gq = ks * 2 + ((lane >> 3) & 1);
                u32 ad = sBB + SWZ(row * 128 + gq * 16);
                asm volatile("ldmatrix.sync.aligned.m8n8.x4.shared.b16 {%0,%1,%2,%3}, [%4];"
                             : "=r"(b[nh][0]), "=r"(b[nh][1]), "=r"(b[nh][2]), "=r"(b[nh][3]) : "r"(ad));
            }
            #pragma unroll
            for (int mi = 0; mi < 2; mi++)
                #pragma unroll
                for (int nh = 0; nh < 2; nh++) {
                    asm volatile("mma.sync.aligned.m16n8k16.row.col.f32.bf16.bf16.f32 "
                                 "{%0,%1,%2,%3}, {%4,%5,%6,%7}, {%8,%9}, {%0,%1,%2,%3};"
                                 : "+f"(acc[mi][nh*2][0]), "+f"(acc[mi][nh*2][1]),
                                   "+f"(acc[mi][nh*2][2]), "+f"(acc[mi][nh*2][3])
                                 : "r"(a[mi][0]), "r"(a[mi][1]), "r"(a[mi][2]), "r"(a[mi][3]),
                                   "r"(b[nh][0]), "r"(b[nh][1]));
                    asm volatile("mma.sync.aligned.m16n8k16.row.col.f32.bf16.bf16.f32 "
                                 "{%0,%1,%2,%3}, {%4,%5,%6,%7}, {%8,%9}, {%0,%1,%2,%3};"
                                 : "+f"(acc[mi][nh*2+1][0]), "+f"(acc[mi][nh*2+1][1]),
                                   "+f"(acc[mi][nh*2+1][2]), "+f"(acc[mi][nh*2+1][3])
                                 : "r"(a[mi][0]), "r"(a[mi][1]), "r"(a[mi][2]), "r"(a[mi][3]),
                                   "r"(b[nh][2]), "r"(b[nh][3]));
                }
        }
        __syncthreads();
    }

    #pragma unroll
    for (int ni = 0; ni < 4; ni++) {
        int c0 = bn + wn * 32 + ni * 8 + (lane & 3) * 2;
        float b0 = bias[c0], b1 = bias[c0 + 1];
        #pragma unroll
        for (int mi = 0; mi < 2; mi++) {
            int r0 = bm + wm * 32 + mi * 16 + (lane >> 2);
            float v0 = acc[mi][ni][0] + b0, v1 = acc[mi][ni][1] + b1;
            float v2 = acc[mi][ni][2] + b0, v3 = acc[mi][ni][3] + b1;
            if (ACT == 1) { v0 = fmaxf(v0, 0.f); v1 = fmaxf(v1, 0.f); v2 = fmaxf(v2, 0.f); v3 = fmaxf(v3, 0.f); }
            if (ACT == 2) { v0 = tanhf(v0); v1 = tanhf(v1); v2 = tanhf(v2); v3 = tanhf(v3); }
            if (WF) {
                *(float2*)(Cf + (size_t)r0 * ldc + c0)       = make_float2(v0, v1);
                *(float2*)(Cf + (size_t)(r0 + 8) * ldc + c0) = make_float2(v2, v3);
            }
            if (WS) {
                __nv_bfloat16* s0 = Cs + (size_t)r0 * ldcs + c0;
                __nv_bfloat16* s1 = Cs + (size_t)(r0 + 8) * ldcs + c0;
                float vv[2][2] = {{v0, v1}, {v2, v3}};
                __nv_bfloat16* sp[2] = {s0, s1};
                #pragma unroll
                for (int rr = 0; rr < 2; rr++)
                    #pragma unroll
                    for (int jj = 0; jj < 2; jj++) {
                        float v = vv[rr][jj];
                        __nv_bfloat16 hi = __float2bfloat16(v);
                        __nv_bfloat16 lo = __float2bfloat16(v - __bfloat162float(hi));
                        sp[rr][jj] = hi; sp[rr][slotC + jj] = hi; sp[rr][2 * slotC + jj] = lo;
                    }
            }
        }
    }
}

// ---------------- neighborhood attention ----------------
__global__ void nbr_kernel() {
    int gwarp = (blockIdx.x * blockDim.x + threadIdx.x) >> 5;
    int lane = threadIdx.x & 31;
    if (gwarp >= NN) return;
    int i = gwarp;
    int r = i >> 6, c = i & 63;

    float hi[16];
    const float* Hi = g_H2 + (size_t)i * H2DIM;
    #pragma unroll
    for (int u = 0; u < 16; u++) hi[u] = Hi[lane + 32 * u];

    int nbrs[8]; int cnt = 0;
    for (int dr = -1; dr <= 1; dr++)
        for (int dc = -1; dc <= 1; dc++) {
            if (dr == 0 && dc == 0) continue;
            int rr = r + dr, cc = c + dc;
            if (rr >= 0 && rr < 32 && cc >= 0 && cc < 64) nbrs[cnt++] = rr * 64 + cc;
        }

    float dots[8];
    for (int q = 0; q < cnt; q++) {
        const float* An = g_An + (size_t)nbrs[q] * HDIM;
        float s = 0.f;
        #pragma unroll
        for (int u = 0; u < 16; u++) s += hi[u] * An[lane + 32 * u];
        #pragma unroll
        for (int o = 16; o; o >>= 1) s += __shfl_xor_sync(0xffffffffu, s, o);
        dots[q] = s;
    }
    float m = -3.0e38f;
    for (int q = 0; q < cnt; q++) m = fmaxf(m, dots[q]);
    float ssum = 0.f;
    for (int q = 0; q < cnt; q++) { dots[q] = expf(dots[q] - m); ssum += dots[q]; }
    float inv = 1.f / ssum;

    float accv[16];
    #pragma unroll
    for (int u = 0; u < 16; u++) accv[u] = 0.f;
    for (int q = 0; q < cnt; q++) {
        float a = dots[q] * inv;
        const float* Hj = g_H2 + (size_t)nbrs[q] * H2DIM;
        #pragma unroll
        for (int u = 0; u < 16; u++) accv[u] += a * Hj[lane + 32 * u];
    }
    float* o = g_H2 + (size_t)i * H2DIM + HDIM;
    __nv_bfloat16* os = g_H2s + (size_t)i * 3 * H2DIM;
    #pragma unroll
    for (int u = 0; u < 16; u++) {
        float v = accv[u];
        int col = 512 + lane + 32 * u;
        o[lane + 32 * u] = v;
        __nv_bfloat16 vh = __float2bfloat16(v);
        __nv_bfloat16 vl = __float2bfloat16(v - __bfloat162float(vh));
        os[col] = vh; os[1024 + col] = vh; os[2048 + col] = vl;
    }
}

// ---------------- template logits (SMEM row cache) ----------------
__global__ void tlogits_kernel(const float* __restrict__ templates) {
    __shared__ float prow[H2DIM];
    int n = blockIdx.x, tid = threadIdx.x;
    const float* p = g_P + (size_t)n * H2DIM;
    for (int i = tid; i < H2DIM; i += 256) prow[i] = p[i];
    __syncthreads();
    int w = tid >> 5, lane = tid & 31;
    for (int t = w; t < TDIM; t += 8) {
        const float* tm = templates + (size_t)t * H2DIM;
        float s = 0.f;
        #pragma unroll 8
        for (int k = lane; k < H2DIM; k += 32) s += prow[k] * tm[k];
        #pragma unroll
        for (int o = 16; o; o >>= 1) s += __shfl_xor_sync(0xffffffffu, s, o);
        if (lane == 0) g_L[t * NN + n] = s;
    }
}

// ---------------- betas softmax ----------------
__global__ void betas_kernel() {
    int t = blockIdx.x, tid = threadIdx.x;
    __shared__ float red[256];
    __shared__ float smax, ssum;
    const float* L = g_L + t * NN;
    float m = -3.0e38f;
    for (int n = tid; n < NN; n += 256) m = fmaxf(m, L[n]);
    red[tid] = m; __syncthreads();
    for (int s = 128; s; s >>= 1) { if (tid < s) red[tid] = fmaxf(red[tid], red[tid + s]); __syncthreads(); }
    if (tid == 0) smax = red[0];
    __syncthreads();
    float acc = 0.f;
    for (int n = tid; n < NN; n += 256) acc += expf(L[n] - smax);
    red[tid] = acc; __syncthreads();
    for (int s = 128; s; s >>= 1) { if (tid < s) red[tid] += red[tid + s]; __syncthreads(); }
    if (tid == 0) ssum = 1.f / red[0];
    __syncthreads();
    for (int n = tid; n < NN; n += 256)
        g_betas[t * NN + n] = expf(L[n] - smax) * ssum;
}

// ---------------- embs partials ----------------
__global__ void embs_part_kernel() {
    __shared__ float bsh[TDIM * 128];
    int col = blockIdx.x * 128 + threadIdx.x;
    int s = blockIdx.y;
    int n0 = s * 128;
    for (int i = threadIdx.x; i < TDIM * 128; i += 128) {
        int t = i >> 7, nl = i & 127;
        bsh[i] = g_betas[t * NN + n0 + nl];
    }
    __syncthreads();
    float acc[TDIM];
    #pragma unroll
    for (int t = 0; t < TDIM; t++) acc[t] = 0.f;
    for (int nl = 0; nl < 128; nl++) {
        float h = g_H2[(size_t)(n0 + nl) * H2DIM + col];
        #pragma unroll
        for (int t = 0; t < TDIM; t++) acc[t] += bsh[t * 128 + nl] * h;
    }
    #pragma unroll
    for (int t = 0; t < TDIM; t++)
        g_embs_part[(size_t)(s * TDIM + t) * H2DIM + col] = acc[t];
}

// ---------------- glob1 (with fused embs reduce) ----------------
__global__ void glob1_kernel(const float* __restrict__ glob_w1, const float* __restrict__ glob_b1) {
    __shared__ float esh[H2DIM];
    int t = blockIdx.y, tid = threadIdx.x;
    for (int k = tid; k < H2DIM; k += 256) {
        float s = 0.f;
        #pragma unroll
        for (int p = 0; p < NSPLIT; p++) s += g_embs_part[(size_t)p * TDIM * H2DIM + t * H2DIM + k];
        esh[k] = s;
        if (blockIdx.x == 0) g_embs[t * H2DIM + k] = s;
    }
    __syncthreads();
    int w = tid >> 5, lane = tid & 31;
    int j = blockIdx.x * 8 + w;
    const float* wr = glob_w1 + (size_t)j * H2DIM;
    float s = 0.f;
    #pragma unroll 8
    for (int k = lane; k < H2DIM; k += 32) s += wr[k] * esh[k];
    #pragma unroll
    for (int o = 16; o; o >>= 1) s += __shfl_xor_sync(0xffffffffu, s, o);
    if (lane == 0) g_V[t * 128 + j] = tanhf(s + glob_b1[j]);
}

// ---------------- final2 ----------------
__global__ void final2_kernel(const float* __restrict__ glob_w2, const float* __restrict__ glob_b2,
                              const float* __restrict__ cls_w,  const float* __restrict__ cls_b,
                              float* __restrict__ out, int out_size) {
    __shared__ float vsh[TDIM * 128];
    __shared__ float Msh[H2DIM];
    __shared__ float gam[TDIM];
    __shared__ float psh[2];
    int tid = threadIdx.x;

    for (int i = tid; i < TDIM * 128; i += 256) vsh[i] = g_V[i];
    __syncthreads();

    if (tid < TDIM) {
        float s = glob_b2[0];
        for (int j = 0; j < 128; j++) s += glob_w2[j] * vsh[tid * 128 + j];
        gam[tid] = s;
    }
    __syncthreads();
    if (tid == 0) {
        float m = gam[0];
        for (int t = 1; t < TDIM; t++) m = fmaxf(m, gam[t]);
        float ss = 0.f;
        for (int t = 0; t < TDIM; t++) { gam[t] = expf(gam[t] - m); ss += gam[t]; }
        float inv = 1.f / ss;
        for (int t = 0; t < TDIM; t++) gam[t] *= inv;
    }
    __syncthreads();

    for (int k = tid; k < H2DIM; k += 256) {
        float s = 0.f;
        #pragma unroll
        for (int t = 0; t < TDIM; t++) s += gam[t] * g_embs[t * H2DIM + k];
        Msh[k] = s;
    }
    __syncthreads();

    if (tid < 64) {
        int c = tid >> 5, lane = tid & 31;
        float s = 0.f;
        for (int k = lane; k < H2DIM; k += 32) s += cls_w[(size_t)c * H2DIM + k] * Msh[k];
        #pragma unroll
        for (int o = 16; o; o >>= 1) s += __shfl_xor_sync(0xffffffffu, s, o);
        if (lane == 0) {
            float p = 1.f / (1.f + expf(-(s + cls_b[c])));
            psh[c] = p;
            if (c < out_size) out[c] = p;
        }
    }
    __syncthreads();
    if (tid == 0 && out_size > 2) out[2] = (psh[1] > psh[0]) ? 1.0f : 0.0f;

    for (int n = tid; n < NN; n += 256) {
        float s = 0.f;
        #pragma unroll
        for (int t = 0; t < TDIM; t++) s += gam[t] * g_betas[t * NN + n];
        if (3 + n < out_size) out[3 + n] = s;
    }
}

// ---------------- launch ----------------
extern "C" void kernel_launch(void* const* d_in, const int* in_sizes, int n_in,
                              void* d_out, int out_size) {
    const float* x        = (const float*)d_in[0];
    const float* conv1_w  = (const float*)d_in[2];
    const float* conv1_b  = (const float*)d_in[3];
    const float* conv2_w  = (const float*)d_in[4];
    const float* conv2_b  = (const float*)d_in[5];
    const float* fc1_w    = (const float*)d_in[6];
    const float* fc1_b    = (const float*)d_in[7];
    const float* fc2_w    = (const float*)d_in[8];
    const float* fc2_b    = (const float*)d_in[9];
    const float* nbr_w    = (const float*)d_in[10];
    const float* nbr_b    = (const float*)d_in[11];
    const float* templates= (const float*)d_in[12];
    const float* proto_w  = (const float*)d_in[13];
    const float* proto_b  = (const float*)d_in[14];
    const float* glob_w1  = (const float*)d_in[15];
    const float* glob_b1  = (const float*)d_in[16];
    const float* glob_w2  = (const float*)d_in[17];
    const float* glob_b2  = (const float*)d_in[18];
    const float* cls_w    = (const float*)d_in[19];
    const float* cls_b    = (const float*)d_in[20];
    float* out = (float*)d_out;

    float *H2, *An, *P;
    __nv_bfloat16 *H0s, *H1s, *H2s, *fc1ws, *fc2ws, *nbrws, *protows;
    cudaGetSymbolAddress((void**)&H2, g_H2);
    cudaGetSymbolAddress((void**)&An, g_An);
    cudaGetSymbolAddress((void**)&P,  g_P);
    cudaGetSymbolAddress((void**)&H0s, g_H0s);
    cudaGetSymbolAddress((void**)&H1s, g_H1s);
    cudaGetSymbolAddress((void**)&H2s, g_H2s);
    cudaGetSymbolAddress((void**)&fc1ws, g_fc1ws);
    cudaGetSymbolAddress((void**)&fc2ws, g_fc2ws);
    cudaGetSymbolAddress((void**)&nbrws, g_nbrws);
    cudaGetSymbolAddress((void**)&protows, g_protows);

    const size_t conv_smem = S_TOTALF * sizeof(float);
    cudaFuncSetAttribute(conv_fused_kernel, cudaFuncAttributeMaxDynamicSharedMemorySize, (int)conv_smem);
    const int gsmem = 4 * STAGE_BYTES;   // 98304
    cudaFuncSetAttribute(mma_gemm<1, false, true>,  cudaFuncAttributeMaxDynamicSharedMemorySize, gsmem);
    cudaFuncSetAttribute(mma_gemm<1, true,  true>,  cudaFuncAttributeMaxDynamicSharedMemorySize, gsmem);
    cudaFuncSetAttribute(mma_gemm<2, true,  false>, cudaFuncAttributeMaxDynamicSharedMemorySize, gsmem);

    conv_fused_kernel<<<NN + CVT_BLOCKS, 512, conv_smem>>>(
        x, conv1_w, conv1_b, conv2_w, conv2_b, fc1_w, fc2_w, nbr_w, proto_w);

    mma_gemm<1, false, true><<<dim3(HDIM / 64, NN / 128), 256, gsmem>>>(
        H0s, fc1ws, fc1_b, nullptr, H1s, H0DIM, 3 * H0DIM, H0DIM, 3 * H0DIM, H0DIM, 0, 3 * HDIM, HDIM);
    mma_gemm<1, true, true><<<dim3(HDIM / 64, NN / 128), 256, gsmem>>>(
        H1s, fc2ws, fc2_b, H2, H2s, HDIM, 3 * HDIM, HDIM, 3 * HDIM, HDIM, H2DIM, 3 * H2DIM, H2DIM);
    mma_gemm<2, true, false><<<dim3(HDIM / 64, NN / 128), 256, gsmem>>>(
        H2s, nbrws, nbr_b, An, nullptr, HDIM, 3 * H2DIM, H2DIM, 3 * HDIM, HDIM, HDIM, 0, 0);
    nbr_kernel<<<NN / 8, 256>>>();
    mma_gemm<2, true, false><<<dim3(H2DIM / 64, NN / 128), 256, gsmem>>>(
        H2s, protows, proto_b, P, nullptr, H2DIM, 3 * H2DIM, H2DIM, 3 * H2DIM, H2DIM, H2DIM, 0, 0);

    tlogits_kernel<<<NN, 256>>>(templates);
    betas_kernel<<<TDIM, 256>>>();
    embs_part_kernel<<<dim3(H2DIM / 128, NSPLIT), 128>>>();
    glob1_kernel<<<dim3(16, TDIM), 256>>>(glob_w1, glob_b1);
    final2_kernel<<<1, 256>>>(glob_w2, glob_b2, cls_w, cls_b, out, out_size);
}